// round 2
// baseline (speedup 1.0000x reference)
#include <cuda_runtime.h>
#include <math.h>

#define BB 2
#define LLE 1024
#define DDIM 1024
#define HH 16
#define DK 64
#define ROWS (BB*LLE)          // 2048
#define OUT_ELEMS (BB*LLE*DDIM)  // 2,097,152

// Scratch (allocation-free rule: __device__ globals)
__device__ float g_qn[ROWS*DDIM];
__device__ float g_q [ROWS*DDIM];
__device__ float g_k [ROWS*DDIM];
__device__ float g_v [ROWS*DDIM];
__device__ float g_ctx[ROWS*DDIM];

// ---------------------------------------------------------------------------
// LayerNorm: one block per row, 256 threads, one float4/thread (D=1024)
// ---------------------------------------------------------------------------
__global__ __launch_bounds__(256)
void ln_kernel(const float* __restrict__ x, const float* __restrict__ gamma,
               const float* __restrict__ beta, float* __restrict__ out)
{
    __shared__ float red[256];
    const int row = blockIdx.x;
    const int tid = threadIdx.x;
    float4 v = ((const float4*)(x + (size_t)row*DDIM))[tid];

    float s = v.x + v.y + v.z + v.w;
    red[tid] = s; __syncthreads();
    #pragma unroll
    for (int o = 128; o > 0; o >>= 1) { if (tid < o) red[tid] += red[tid+o]; __syncthreads(); }
    const float mean = red[0] * (1.0f/DDIM);
    __syncthreads();

    float dx0 = v.x-mean, dx1 = v.y-mean, dx2 = v.z-mean, dx3 = v.w-mean;
    float s2 = dx0*dx0 + dx1*dx1 + dx2*dx2 + dx3*dx3;
    red[tid] = s2; __syncthreads();
    #pragma unroll
    for (int o = 128; o > 0; o >>= 1) { if (tid < o) red[tid] += red[tid+o]; __syncthreads(); }
    const float var = red[0] * (1.0f/DDIM);
    const float rstd = rsqrtf(var + 1e-6f);

    float4 g = ((const float4*)gamma)[tid];
    float4 b = ((const float4*)beta )[tid];
    float4 o4;
    o4.x = dx0*rstd*g.x + b.x;
    o4.y = dx1*rstd*g.y + b.y;
    o4.z = dx2*rstd*g.z + b.z;
    o4.w = dx3*rstd*g.w + b.w;
    ((float4*)(out + (size_t)row*DDIM))[tid] = o4;
}

// ---------------------------------------------------------------------------
// NT SGEMM: C[M,N] = A[M,K] @ W[N,K]^T + bias[N] (+ residual[M,N])
// 128x128x8 tiles, 256 threads, 8x8 per thread as 2x2 float4 quadrants.
// M,N,K all multiples of 128 here -> no bounds checks.
// ---------------------------------------------------------------------------
__global__ __launch_bounds__(256)
void gemm_nt_kernel(const float* __restrict__ A, const float* __restrict__ W,
                    const float* __restrict__ bias, const float* __restrict__ resid,
                    float* __restrict__ C, int M, int N, int K)
{
    __shared__ float As[8][128];
    __shared__ float Bs[8][128];

    const int tid = threadIdx.x;
    const int tx  = tid & 15;
    const int ty  = tid >> 4;
    const int rowBase = blockIdx.y * 128;
    const int colBase = blockIdx.x * 128;

    const int lr = tid >> 1;        // 0..127
    const int lc = (tid & 1) * 4;   // 0 or 4
    const float* Ap = A + (size_t)(rowBase + lr) * K + lc;
    const float* Wp = W + (size_t)(colBase + lr) * K + lc;

    float acc[8][8];
    #pragma unroll
    for (int i = 0; i < 8; i++)
        #pragma unroll
        for (int j = 0; j < 8; j++) acc[i][j] = 0.0f;

    for (int k0 = 0; k0 < K; k0 += 8) {
        float4 a = *(const float4*)(Ap + k0);
        float4 w = *(const float4*)(Wp + k0);
        __syncthreads();
        As[lc+0][lr] = a.x; As[lc+1][lr] = a.y; As[lc+2][lr] = a.z; As[lc+3][lr] = a.w;
        Bs[lc+0][lr] = w.x; Bs[lc+1][lr] = w.y; Bs[lc+2][lr] = w.z; Bs[lc+3][lr] = w.w;
        __syncthreads();

        #pragma unroll
        for (int k = 0; k < 8; k++) {
            float4 a0 = *(const float4*)&As[k][ty*4];
            float4 a1 = *(const float4*)&As[k][64 + ty*4];
            float4 b0 = *(const float4*)&Bs[k][tx*4];
            float4 b1 = *(const float4*)&Bs[k][64 + tx*4];
            float ra[8] = {a0.x,a0.y,a0.z,a0.w, a1.x,a1.y,a1.z,a1.w};
            float rb[8] = {b0.x,b0.y,b0.z,b0.w, b1.x,b1.y,b1.z,b1.w};
            #pragma unroll
            for (int i = 0; i < 8; i++)
                #pragma unroll
                for (int j = 0; j < 8; j++)
                    acc[i][j] += ra[i] * rb[j];
        }
    }

    #pragma unroll
    for (int ii = 0; ii < 2; ii++) {
        #pragma unroll
        for (int i = 0; i < 4; i++) {
            const int row = rowBase + ii*64 + ty*4 + i;
            #pragma unroll
            for (int jj = 0; jj < 2; jj++) {
                const int col = colBase + jj*64 + tx*4;
                float4 bz = *(const float4*)&bias[col];
                float4 o;
                o.x = acc[ii*4+i][jj*4+0] + bz.x;
                o.y = acc[ii*4+i][jj*4+1] + bz.y;
                o.z = acc[ii*4+i][jj*4+2] + bz.z;
                o.w = acc[ii*4+i][jj*4+3] + bz.w;
                if (resid) {
                    float4 rr = *(const float4*)&resid[(size_t)row*N + col];
                    o.x += rr.x; o.y += rr.y; o.z += rr.z; o.w += rr.w;
                }
                *(float4*)&C[(size_t)row*N + col] = o;
            }
        }
    }
}

// ---------------------------------------------------------------------------
// Logits: S[b,h,q,s] = (Q·K)/8 + pos_bias + postag_bias + lex; mask==0 -> -1e30
// 64x64 tile per block, dk=64 fully staged in smem, 4x4 per thread.
// ---------------------------------------------------------------------------
__global__ __launch_bounds__(256)
void logits_kernel(const float* __restrict__ Q, const float* __restrict__ Kt,
                   const float* __restrict__ pos_bias, const float* __restrict__ postag,
                   const float* __restrict__ lex, const int* __restrict__ mask,
                   float* __restrict__ attn)
{
    __shared__ float Qs[64][68];
    __shared__ float Ks[64][68];

    const int tid = threadIdx.x;
    const int tx  = tid & 15;
    const int ty  = tid >> 4;
    const int sBase = blockIdx.x * 64;
    const int qBase = blockIdx.y * 64;
    const int bh = blockIdx.z;
    const int b = bh >> 4, h = bh & 15;

    {
        const int c = tx * 4;
        #pragma unroll
        for (int rr = 0; rr < 4; rr++) {
            const int r = rr*16 + ty;
            float4 qv = *(const float4*)&Q [((size_t)(b*LLE + qBase + r))*DDIM + h*DK + c];
            float4 kv = *(const float4*)&Kt[((size_t)(b*LLE + sBase + r))*DDIM + h*DK + c];
            *(float4*)&Qs[r][c] = qv;
            *(float4*)&Ks[r][c] = kv;
        }
    }
    __syncthreads();

    float acc[4][4];
    #pragma unroll
    for (int i = 0; i < 4; i++)
        #pragma unroll
        for (int j = 0; j < 4; j++) acc[i][j] = 0.0f;

    #pragma unroll
    for (int k = 0; k < 64; k += 4) {
        float4 qv[4], kv[4];
        #pragma unroll
        for (int i = 0; i < 4; i++) qv[i] = *(const float4*)&Qs[ty*4+i][k];
        #pragma unroll
        for (int j = 0; j < 4; j++) kv[j] = *(const float4*)&Ks[tx*4+j][k];
        #pragma unroll
        for (int i = 0; i < 4; i++)
            #pragma unroll
            for (int j = 0; j < 4; j++)
                acc[i][j] += qv[i].x*kv[j].x + qv[i].y*kv[j].y
                           + qv[i].z*kv[j].z + qv[i].w*kv[j].w;
    }

    const float SCALE_INV = 0.125f;   // 1/sqrt(64)
    const int s = sBase + tx*4;
    const float4 lx = *(const float4*)&lex[b*LLE + s];
    const int4  mk = *(const int4 *)&mask[b*LLE + s];
    const size_t bhLL = (size_t)bh * LLE;

    #pragma unroll
    for (int i = 0; i < 4; i++) {
        const int q = qBase + ty*4 + i;
        float4 pb = *(const float4*)&pos_bias[((size_t)h*LLE + q)*LLE + s];
        float4 pt = *(const float4*)&postag  [(bhLL + q)*LLE + s];
        float4 o;
        o.x = (mk.x == 0) ? -1e30f : (acc[i][0]*SCALE_INV + pb.x + pt.x + lx.x);
        o.y = (mk.y == 0) ? -1e30f : (acc[i][1]*SCALE_INV + pb.y + pt.y + lx.y);
        o.z = (mk.z == 0) ? -1e30f : (acc[i][2]*SCALE_INV + pb.z + pt.z + lx.z);
        o.w = (mk.w == 0) ? -1e30f : (acc[i][3]*SCALE_INV + pb.w + pt.w + lx.w);
        *(float4*)&attn[(bhLL + q)*LLE + s] = o;
    }
}

// ---------------------------------------------------------------------------
// Row softmax in place (row length 1024), one block per (b,h,q) row.
// ---------------------------------------------------------------------------
__global__ __launch_bounds__(256)
void softmax_kernel(float* __restrict__ attn)
{
    __shared__ float red[256];
    const size_t row = blockIdx.x;
    const int tid = threadIdx.x;
    float4* p = (float4*)(attn + row * LLE);
    float4 v = p[tid];

    float m = fmaxf(fmaxf(v.x, v.y), fmaxf(v.z, v.w));
    red[tid] = m; __syncthreads();
    #pragma unroll
    for (int o = 128; o > 0; o >>= 1) { if (tid < o) red[tid] = fmaxf(red[tid], red[tid+o]); __syncthreads(); }
    m = red[0];
    __syncthreads();

    float4 e;
    e.x = expf(v.x - m); e.y = expf(v.y - m);
    e.z = expf(v.z - m); e.w = expf(v.w - m);
    float s = e.x + e.y + e.z + e.w;
    red[tid] = s; __syncthreads();
    #pragma unroll
    for (int o = 128; o > 0; o >>= 1) { if (tid < o) red[tid] += red[tid+o]; __syncthreads(); }
    const float inv = 1.0f / red[0];

    e.x *= inv; e.y *= inv; e.z *= inv; e.w *= inv;
    p[tid] = e;
}

// ---------------------------------------------------------------------------
// AV: ctx[b,q,h*64+n] = sum_s attn[b,h,q,s] * V[b,s,h*64+n]
// 64(q) x 64(n) x 32(k) tiles per block, 4x4 per thread.
// ---------------------------------------------------------------------------
__global__ __launch_bounds__(256)
void av_kernel(const float* __restrict__ attn, const float* __restrict__ V,
               float* __restrict__ ctx)
{
    __shared__ float As[64][36];  // [q][k]
    __shared__ float Bs[64][36];  // [n][k] (V transposed)

    const int tid = threadIdx.x;
    const int tx  = tid & 15;
    const int ty  = tid >> 4;
    const int qBase = blockIdx.x * 64;
    const int bh = blockIdx.y;
    const int b = bh >> 4, h = bh & 15;

    const float* Arow = attn + ((size_t)bh * LLE + qBase) * LLE;

    float acc[4][4];
    #pragma unroll
    for (int i = 0; i < 4; i++)
        #pragma unroll
        for (int j = 0; j < 4; j++) acc[i][j] = 0.0f;

    for (int k0 = 0; k0 < LLE; k0 += 32) {
        __syncthreads();
        {
            const int r0 = tid >> 3;        // 0..31
            const int c  = (tid & 7) * 4;   // 0..28
            #pragma unroll
            for (int rr = 0; rr < 2; rr++) {
                const int r = rr*32 + r0;
                float4 a = *(const float4*)&Arow[(size_t)r*LLE + k0 + c];
                *(float4*)&As[r][c] = a;
            }
            const int kk = tid >> 4;        // 0..15
            const int cn = (tid & 15) * 4;  // 0..60
            #pragma unroll
            for (int rr = 0; rr < 2; rr++) {
                const int k = rr*16 + kk;
                float4 vv = *(const float4*)&V[((size_t)(b*LLE + k0 + k))*DDIM + h*DK + cn];
                Bs[cn+0][k] = vv.x; Bs[cn+1][k] = vv.y;
                Bs[cn+2][k] = vv.z; Bs[cn+3][k] = vv.w;
            }
        }
        __syncthreads();

        #pragma unroll
        for (int k = 0; k < 32; k += 4) {
            float4 av[4], bv[4];
            #pragma unroll
            for (int i = 0; i < 4; i++) av[i] = *(const float4*)&As[ty*4+i][k];
            #pragma unroll
            for (int j = 0; j < 4; j++) bv[j] = *(const float4*)&Bs[tx*4+j][k];
            #pragma unroll
            for (int i = 0; i < 4; i++)
                #pragma unroll
                for (int j = 0; j < 4; j++)
                    acc[i][j] += av[i].x*bv[j].x + av[i].y*bv[j].y
                               + av[i].z*bv[j].z + av[i].w*bv[j].w;
        }
    }

    const int n = tx * 4;
    #pragma unroll
    for (int i = 0; i < 4; i++) {
        const int q = qBase + ty*4 + i;
        float4 o = {acc[i][0], acc[i][1], acc[i][2], acc[i][3]};
        *(float4*)&ctx[((size_t)(b*LLE + q))*DDIM + h*DK + n] = o;
    }
}

// ---------------------------------------------------------------------------
extern "C" void kernel_launch(void* const* d_in, const int* in_sizes, int n_in,
                              void* d_out, int out_size)
{
    const float* query  = (const float*)d_in[0];
    const float* pos_b  = (const float*)d_in[1];
    const float* postag = (const float*)d_in[2];
    const float* lex    = (const float*)d_in[3];
    const int*   mask   = (const int*  )d_in[4];
    const float* Wq = (const float*)d_in[5];
    const float* bq = (const float*)d_in[6];
    const float* Wk = (const float*)d_in[7];
    const float* bk = (const float*)d_in[8];
    const float* Wv = (const float*)d_in[9];
    const float* bv = (const float*)d_in[10];
    const float* Wo = (const float*)d_in[11];
    const float* bo = (const float*)d_in[12];
    const float* gamma = (const float*)d_in[13];
    const float* beta  = (const float*)d_in[14];

    float* out  = (float*)d_out;            // (B,L,D)
    float* attn = (float*)d_out + OUT_ELEMS; // (B,H,L,L)

    float* qn  = nullptr; cudaGetSymbolAddress((void**)&qn,  g_qn);
    float* Qm  = nullptr; cudaGetSymbolAddress((void**)&Qm,  g_q);
    float* Km  = nullptr; cudaGetSymbolAddress((void**)&Km,  g_k);
    float* Vm  = nullptr; cudaGetSymbolAddress((void**)&Vm,  g_v);
    float* ctx = nullptr; cudaGetSymbolAddress((void**)&ctx, g_ctx);

    // 1) pre-LN on query only
    ln_kernel<<<ROWS, 256>>>(query, gamma, beta, qn);

    // 2) projections: Q from qn; K,V from raw query (context set before norm)
    dim3 ggrid(DDIM/128, ROWS/128);
    gemm_nt_kernel<<<ggrid, 256>>>(qn,    Wq, bq, nullptr, Qm, ROWS, DDIM, DDIM);
    gemm_nt_kernel<<<ggrid, 256>>>(query, Wk, bk, nullptr, Km, ROWS, DDIM, DDIM);
    gemm_nt_kernel<<<ggrid, 256>>>(query, Wv, bv, nullptr, Vm, ROWS, DDIM, DDIM);

    // 3) logits + biases + mask  -> attn region
    dim3 lgrid(LLE/64, LLE/64, BB*HH);
    logits_kernel<<<lgrid, 256>>>(Qm, Km, pos_b, postag, lex, mask, attn);

    // 4) softmax in place
    softmax_kernel<<<BB*HH*LLE, 256>>>(attn);

    // 5) ctx = attn @ V
    dim3 agrid(LLE/64, BB*HH);
    av_kernel<<<agrid, 256>>>(attn, Vm, ctx);

    // 6) out = ctx @ Wo^T + bo + residual(query)
    gemm_nt_kernel<<<ggrid, 256>>>(ctx, Wo, bo, query, out, ROWS, DDIM, DDIM);
}

// round 3
// speedup vs baseline: 1.4445x; 1.4445x over previous
#include <cuda_runtime.h>
#include <math.h>

#define BB 2
#define LLE 1024
#define DDIM 1024
#define HH 16
#define DK 64
#define ROWS (BB*LLE)            // 2048
#define OUT_ELEMS (BB*LLE*DDIM)  // 2,097,152

// Scratch (allocation-free rule: __device__ globals)
__device__ float g_qn[ROWS*DDIM];
__device__ float g_q [ROWS*DDIM];
__device__ float g_k [ROWS*DDIM];
__device__ float g_v [ROWS*DDIM];
__device__ float g_ctx[ROWS*DDIM];

// ---------------------------------------------------------------------------
// helpers: tf32 convert + mma.m16n8k8 tf32
// ---------------------------------------------------------------------------
__device__ __forceinline__ unsigned tf32_bits(float x) {
    unsigned u;
    asm("cvt.rna.tf32.f32 %0, %1;" : "=r"(u) : "f"(x));
    return u;
}

__device__ __forceinline__ void mma_tf32(float acc[4], const unsigned a[4], const unsigned b[2]) {
    asm volatile(
        "mma.sync.aligned.m16n8k8.row.col.f32.tf32.tf32.f32 "
        "{%0,%1,%2,%3}, {%4,%5,%6,%7}, {%8,%9}, {%0,%1,%2,%3};"
        : "+f"(acc[0]), "+f"(acc[1]), "+f"(acc[2]), "+f"(acc[3])
        : "r"(a[0]), "r"(a[1]), "r"(a[2]), "r"(a[3]), "r"(b[0]), "r"(b[1]));
}

// ---------------------------------------------------------------------------
// LayerNorm: one block per row, 256 threads, one float4/thread (D=1024)
// ---------------------------------------------------------------------------
__global__ __launch_bounds__(256)
void ln_kernel(const float* __restrict__ x, const float* __restrict__ gamma,
               const float* __restrict__ beta, float* __restrict__ out)
{
    __shared__ float red[256];
    const int row = blockIdx.x;
    const int tid = threadIdx.x;
    float4 v = ((const float4*)(x + (size_t)row*DDIM))[tid];

    float s = v.x + v.y + v.z + v.w;
    red[tid] = s; __syncthreads();
    #pragma unroll
    for (int o = 128; o > 0; o >>= 1) { if (tid < o) red[tid] += red[tid+o]; __syncthreads(); }
    const float mean = red[0] * (1.0f/DDIM);
    __syncthreads();

    float dx0 = v.x-mean, dx1 = v.y-mean, dx2 = v.z-mean, dx3 = v.w-mean;
    float s2 = dx0*dx0 + dx1*dx1 + dx2*dx2 + dx3*dx3;
    red[tid] = s2; __syncthreads();
    #pragma unroll
    for (int o = 128; o > 0; o >>= 1) { if (tid < o) red[tid] += red[tid+o]; __syncthreads(); }
    const float var = red[0] * (1.0f/DDIM);
    const float rstd = rsqrtf(var + 1e-6f);

    float4 g = ((const float4*)gamma)[tid];
    float4 b = ((const float4*)beta )[tid];
    float4 o4;
    o4.x = dx0*rstd*g.x + b.x;
    o4.y = dx1*rstd*g.y + b.y;
    o4.z = dx2*rstd*g.z + b.z;
    o4.w = dx3*rstd*g.w + b.w;
    ((float4*)(out + (size_t)row*DDIM))[tid] = o4;
}

// ---------------------------------------------------------------------------
// tf32 tensor-core NT GEMM: C[M,N] = A[M,K] @ W[N,K]^T + bias[N] (+ resid)
// 128x128 block tile, k-step 16, double-buffered, 8 warps (warp tile 32x64).
// Smem stride 20 floats -> conflict-free 32-bit fragment loads.
// ---------------------------------------------------------------------------
#define SSTR 20

__global__ __launch_bounds__(256)
void gemm_tf32_nt(const float* __restrict__ A, const float* __restrict__ W,
                  const float* __restrict__ bias, const float* __restrict__ resid,
                  float* __restrict__ C, int M, int N, int K)
{
    __shared__ float As[2][128*SSTR];
    __shared__ float Bs[2][128*SSTR];

    const int tid  = threadIdx.x;
    const int lane = tid & 31;
    const int warp = tid >> 5;
    const int wm   = warp & 3;   // 0..3 : 32-row slab
    const int wn   = warp >> 2;  // 0..1 : 64-col slab
    const int gid  = lane >> 2;  // group id 0..7
    const int tig  = lane & 3;   // thread in group 0..3

    const int rowBase = blockIdx.y * 128;
    const int colBase = blockIdx.x * 128;

    // global staging: each thread 2x float4 from A and from W per 16-k step
    const int lr = tid >> 2;        // 0..63  (rows lr and lr+64)
    const int lc = (tid & 3) * 4;   // 0,4,8,12
    const float* Ag = A + (size_t)(rowBase + lr) * K + lc;
    const float* Wg = W + (size_t)(colBase + lr) * K + lc;

    float acc[2][8][4];
    #pragma unroll
    for (int mt = 0; mt < 2; mt++)
        #pragma unroll
        for (int nt = 0; nt < 8; nt++)
            #pragma unroll
            for (int c = 0; c < 4; c++) acc[mt][nt][c] = 0.0f;

    float4 pa0, pa1, pb0, pb1;

    // ---- prefetch k=0 and stage ----
    pa0 = *(const float4*)(Ag);
    pa1 = *(const float4*)(Ag + (size_t)64*K);
    pb0 = *(const float4*)(Wg);
    pb1 = *(const float4*)(Wg + (size_t)64*K);
    {
        float* a0 = &As[0][lr*SSTR + lc];
        float* a1 = a0 + 64*SSTR;
        a0[0]=__uint_as_float(tf32_bits(pa0.x)); a0[1]=__uint_as_float(tf32_bits(pa0.y));
        a0[2]=__uint_as_float(tf32_bits(pa0.z)); a0[3]=__uint_as_float(tf32_bits(pa0.w));
        a1[0]=__uint_as_float(tf32_bits(pa1.x)); a1[1]=__uint_as_float(tf32_bits(pa1.y));
        a1[2]=__uint_as_float(tf32_bits(pa1.z)); a1[3]=__uint_as_float(tf32_bits(pa1.w));
        float* b0 = &Bs[0][lr*SSTR + lc];
        float* b1 = b0 + 64*SSTR;
        b0[0]=__uint_as_float(tf32_bits(pb0.x)); b0[1]=__uint_as_float(tf32_bits(pb0.y));
        b0[2]=__uint_as_float(tf32_bits(pb0.z)); b0[3]=__uint_as_float(tf32_bits(pb0.w));
        b1[0]=__uint_as_float(tf32_bits(pb1.x)); b1[1]=__uint_as_float(tf32_bits(pb1.y));
        b1[2]=__uint_as_float(tf32_bits(pb1.z)); b1[3]=__uint_as_float(tf32_bits(pb1.w));
    }
    __syncthreads();

    int buf = 0;
    for (int k0 = 0; k0 < K; k0 += 16) {
        const bool hasNext = (k0 + 16) < K;
        if (hasNext) {
            pa0 = *(const float4*)(Ag + k0 + 16);
            pa1 = *(const float4*)(Ag + (size_t)64*K + k0 + 16);
            pb0 = *(const float4*)(Wg + k0 + 16);
            pb1 = *(const float4*)(Wg + (size_t)64*K + k0 + 16);
        }

        // compute on buf (two k8 sub-steps)
        #pragma unroll
        for (int ks = 0; ks < 16; ks += 8) {
            unsigned afr[2][4];
            #pragma unroll
            for (int mt = 0; mt < 2; mt++) {
                const float* ap = &As[buf][(wm*32 + mt*16)*SSTR + ks];
                afr[mt][0] = __float_as_uint(ap[ gid     *SSTR + tig    ]);
                afr[mt][1] = __float_as_uint(ap[(gid + 8)*SSTR + tig    ]);
                afr[mt][2] = __float_as_uint(ap[ gid     *SSTR + tig + 4]);
                afr[mt][3] = __float_as_uint(ap[(gid + 8)*SSTR + tig + 4]);
            }
            unsigned bfr[8][2];
            #pragma unroll
            for (int nt = 0; nt < 8; nt++) {
                const float* bp = &Bs[buf][(wn*64 + nt*8)*SSTR + ks];
                bfr[nt][0] = __float_as_uint(bp[gid*SSTR + tig    ]);
                bfr[nt][1] = __float_as_uint(bp[gid*SSTR + tig + 4]);
            }
            #pragma unroll
            for (int mt = 0; mt < 2; mt++)
                #pragma unroll
                for (int nt = 0; nt < 8; nt++)
                    mma_tf32(acc[mt][nt], afr[mt], bfr[nt]);
        }

        if (hasNext) {
            const int nb = buf ^ 1;
            float* a0 = &As[nb][lr*SSTR + lc];
            float* a1 = a0 + 64*SSTR;
            a0[0]=__uint_as_float(tf32_bits(pa0.x)); a0[1]=__uint_as_float(tf32_bits(pa0.y));
            a0[2]=__uint_as_float(tf32_bits(pa0.z)); a0[3]=__uint_as_float(tf32_bits(pa0.w));
            a1[0]=__uint_as_float(tf32_bits(pa1.x)); a1[1]=__uint_as_float(tf32_bits(pa1.y));
            a1[2]=__uint_as_float(tf32_bits(pa1.z)); a1[3]=__uint_as_float(tf32_bits(pa1.w));
            float* b0 = &Bs[nb][lr*SSTR + lc];
            float* b1 = b0 + 64*SSTR;
            b0[0]=__uint_as_float(tf32_bits(pb0.x)); b0[1]=__uint_as_float(tf32_bits(pb0.y));
            b0[2]=__uint_as_float(tf32_bits(pb0.z)); b0[3]=__uint_as_float(tf32_bits(pb0.w));
            b1[0]=__uint_as_float(tf32_bits(pb1.x)); b1[1]=__uint_as_float(tf32_bits(pb1.y));
            b1[2]=__uint_as_float(tf32_bits(pb1.z)); b1[3]=__uint_as_float(tf32_bits(pb1.w));
            __syncthreads();
            buf = nb;
        }
    }

    // epilogue
    #pragma unroll
    for (int nt = 0; nt < 8; nt++) {
        const int col = colBase + wn*64 + nt*8 + tig*2;
        float2 bz = *(const float2*)&bias[col];
        #pragma unroll
        for (int mt = 0; mt < 2; mt++) {
            const int r0 = rowBase + wm*32 + mt*16 + gid;
            const int r1 = r0 + 8;
            float2 v0 = { acc[mt][nt][0] + bz.x, acc[mt][nt][1] + bz.y };
            float2 v1 = { acc[mt][nt][2] + bz.x, acc[mt][nt][3] + bz.y };
            if (resid) {
                float2 q0 = *(const float2*)&resid[(size_t)r0*N + col];
                float2 q1 = *(const float2*)&resid[(size_t)r1*N + col];
                v0.x += q0.x; v0.y += q0.y;
                v1.x += q1.x; v1.y += q1.y;
            }
            *(float2*)&C[(size_t)r0*N + col] = v0;
            *(float2*)&C[(size_t)r1*N + col] = v1;
        }
    }
}

// ---------------------------------------------------------------------------
// Logits: S[b,h,q,s] = (Q·K)/8 + pos_bias + postag_bias + lex; mask==0 -> -1e30
// 64x64 tile per block, dk=64 fully staged in smem, 4x4 per thread.
// ---------------------------------------------------------------------------
__global__ __launch_bounds__(256)
void logits_kernel(const float* __restrict__ Q, const float* __restrict__ Kt,
                   const float* __restrict__ pos_bias, const float* __restrict__ postag,
                   const float* __restrict__ lex, const int* __restrict__ mask,
                   float* __restrict__ attn)
{
    __shared__ float Qs[64][68];
    __shared__ float Ks[64][68];

    const int tid = threadIdx.x;
    const int tx  = tid & 15;
    const int ty  = tid >> 4;
    const int sBase = blockIdx.x * 64;
    const int qBase = blockIdx.y * 64;
    const int bh = blockIdx.z;
    const int b = bh >> 4, h = bh & 15;

    {
        const int c = tx * 4;
        #pragma unroll
        for (int rr = 0; rr < 4; rr++) {
            const int r = rr*16 + ty;
            float4 qv = *(const float4*)&Q [((size_t)(b*LLE + qBase + r))*DDIM + h*DK + c];
            float4 kv = *(const float4*)&Kt[((size_t)(b*LLE + sBase + r))*DDIM + h*DK + c];
            *(float4*)&Qs[r][c] = qv;
            *(float4*)&Ks[r][c] = kv;
        }
    }
    __syncthreads();

    float acc[4][4];
    #pragma unroll
    for (int i = 0; i < 4; i++)
        #pragma unroll
        for (int j = 0; j < 4; j++) acc[i][j] = 0.0f;

    #pragma unroll
    for (int k = 0; k < 64; k += 4) {
        float4 qv[4], kv[4];
        #pragma unroll
        for (int i = 0; i < 4; i++) qv[i] = *(const float4*)&Qs[ty*4+i][k];
        #pragma unroll
        for (int j = 0; j < 4; j++) kv[j] = *(const float4*)&Ks[tx*4+j][k];
        #pragma unroll
        for (int i = 0; i < 4; i++)
            #pragma unroll
            for (int j = 0; j < 4; j++)
                acc[i][j] += qv[i].x*kv[j].x + qv[i].y*kv[j].y
                           + qv[i].z*kv[j].z + qv[i].w*kv[j].w;
    }

    const float SCALE_INV = 0.125f;   // 1/sqrt(64)
    const int s = sBase + tx*4;
    const float4 lx = *(const float4*)&lex[b*LLE + s];
    const int4  mk = *(const int4 *)&mask[b*LLE + s];
    const size_t bhLL = (size_t)bh * LLE;

    #pragma unroll
    for (int i = 0; i < 4; i++) {
        const int q = qBase + ty*4 + i;
        float4 pb = *(const float4*)&pos_bias[((size_t)h*LLE + q)*LLE + s];
        float4 pt = *(const float4*)&postag  [(bhLL + q)*LLE + s];
        float4 o;
        o.x = (mk.x == 0) ? -1e30f : (acc[i][0]*SCALE_INV + pb.x + pt.x + lx.x);
        o.y = (mk.y == 0) ? -1e30f : (acc[i][1]*SCALE_INV + pb.y + pt.y + lx.y);
        o.z = (mk.z == 0) ? -1e30f : (acc[i][2]*SCALE_INV + pb.z + pt.z + lx.z);
        o.w = (mk.w == 0) ? -1e30f : (acc[i][3]*SCALE_INV + pb.w + pt.w + lx.w);
        *(float4*)&attn[(bhLL + q)*LLE + s] = o;
    }
}

// ---------------------------------------------------------------------------
// Row softmax in place (row length 1024), one block per (b,h,q) row.
// ---------------------------------------------------------------------------
__global__ __launch_bounds__(256)
void softmax_kernel(float* __restrict__ attn)
{
    __shared__ float red[256];
    const size_t row = blockIdx.x;
    const int tid = threadIdx.x;
    float4* p = (float4*)(attn + row * LLE);
    float4 v = p[tid];

    float m = fmaxf(fmaxf(v.x, v.y), fmaxf(v.z, v.w));
    red[tid] = m; __syncthreads();
    #pragma unroll
    for (int o = 128; o > 0; o >>= 1) { if (tid < o) red[tid] = fmaxf(red[tid], red[tid+o]); __syncthreads(); }
    m = red[0];
    __syncthreads();

    float4 e;
    e.x = expf(v.x - m); e.y = expf(v.y - m);
    e.z = expf(v.z - m); e.w = expf(v.w - m);
    float s = e.x + e.y + e.z + e.w;
    red[tid] = s; __syncthreads();
    #pragma unroll
    for (int o = 128; o > 0; o >>= 1) { if (tid < o) red[tid] += red[tid+o]; __syncthreads(); }
    const float inv = 1.0f / red[0];

    e.x *= inv; e.y *= inv; e.z *= inv; e.w *= inv;
    p[tid] = e;
}

// ---------------------------------------------------------------------------
// AV: ctx[b,q,h*64+n] = sum_s attn[b,h,q,s] * V[b,s,h*64+n]
// ---------------------------------------------------------------------------
__global__ __launch_bounds__(256)
void av_kernel(const float* __restrict__ attn, const float* __restrict__ V,
               float* __restrict__ ctx)
{
    __shared__ float As_[64][36];  // [q][k]
    __shared__ float Bs_[64][36];  // [n][k] (V transposed)

    const int tid = threadIdx.x;
    const int tx  = tid & 15;
    const int ty  = tid >> 4;
    const int qBase = blockIdx.x * 64;
    const int bh = blockIdx.y;
    const int b = bh >> 4, h = bh & 15;

    const float* Arow = attn + ((size_t)bh * LLE + qBase) * LLE;

    float acc[4][4];
    #pragma unroll
    for (int i = 0; i < 4; i++)
        #pragma unroll
        for (int j = 0; j < 4; j++) acc[i][j] = 0.0f;

    for (int k0 = 0; k0 < LLE; k0 += 32) {
        __syncthreads();
        {
            const int r0 = tid >> 3;
            const int c  = (tid & 7) * 4;
            #pragma unroll
            for (int rr = 0; rr < 2; rr++) {
                const int r = rr*32 + r0;
                float4 a = *(const float4*)&Arow[(size_t)r*LLE + k0 + c];
                *(float4*)&As_[r][c] = a;
            }
            const int kk = tid >> 4;
            const int cn = (tid & 15) * 4;
            #pragma unroll
            for (int rr = 0; rr < 2; rr++) {
                const int k = rr*16 + kk;
                float4 vv = *(const float4*)&V[((size_t)(b*LLE + k0 + k))*DDIM + h*DK + cn];
                Bs_[cn+0][k] = vv.x; Bs_[cn+1][k] = vv.y;
                Bs_[cn+2][k] = vv.z; Bs_[cn+3][k] = vv.w;
            }
        }
        __syncthreads();

        #pragma unroll
        for (int k = 0; k < 32; k += 4) {
            float4 av[4], bv[4];
            #pragma unroll
            for (int i = 0; i < 4; i++) av[i] = *(const float4*)&As_[ty*4+i][k];
            #pragma unroll
            for (int j = 0; j < 4; j++) bv[j] = *(const float4*)&Bs_[tx*4+j][k];
            #pragma unroll
            for (int i = 0; i < 4; i++)
                #pragma unroll
                for (int j = 0; j < 4; j++)
                    acc[i][j] += av[i].x*bv[j].x + av[i].y*bv[j].y
                               + av[i].z*bv[j].z + av[i].w*bv[j].w;
        }
    }

    const int n = tx * 4;
    #pragma unroll
    for (int i = 0; i < 4; i++) {
        const int q = qBase + ty*4 + i;
        float4 o = {acc[i][0], acc[i][1], acc[i][2], acc[i][3]};
        *(float4*)&ctx[((size_t)(b*LLE + q))*DDIM + h*DK + n] = o;
    }
}

// ---------------------------------------------------------------------------
extern "C" void kernel_launch(void* const* d_in, const int* in_sizes, int n_in,
                              void* d_out, int out_size)
{
    const float* query  = (const float*)d_in[0];
    const float* pos_b  = (const float*)d_in[1];
    const float* postag = (const float*)d_in[2];
    const float* lex    = (const float*)d_in[3];
    const int*   mask   = (const int*  )d_in[4];
    const float* Wq = (const float*)d_in[5];
    const float* bq = (const float*)d_in[6];
    const float* Wk = (const float*)d_in[7];
    const float* bk = (const float*)d_in[8];
    const float* Wv = (const float*)d_in[9];
    const float* bv = (const float*)d_in[10];
    const float* Wo = (const float*)d_in[11];
    const float* bo = (const float*)d_in[12];
    const float* gamma = (const float*)d_in[13];
    const float* beta  = (const float*)d_in[14];

    float* out  = (float*)d_out;             // (B,L,D)
    float* attn = (float*)d_out + OUT_ELEMS; // (B,H,L,L)

    float* qn  = nullptr; cudaGetSymbolAddress((void**)&qn,  g_qn);
    float* Qm  = nullptr; cudaGetSymbolAddress((void**)&Qm,  g_q);
    float* Km  = nullptr; cudaGetSymbolAddress((void**)&Km,  g_k);
    float* Vm  = nullptr; cudaGetSymbolAddress((void**)&Vm,  g_v);
    float* ctx = nullptr; cudaGetSymbolAddress((void**)&ctx, g_ctx);

    // 1) pre-LN on query only
    ln_kernel<<<ROWS, 256>>>(query, gamma, beta, qn);

    // 2) projections: Q from qn; K,V from raw query (context set before norm)
    dim3 ggrid(DDIM/128, ROWS/128);
    gemm_tf32_nt<<<ggrid, 256>>>(qn,    Wq, bq, nullptr, Qm, ROWS, DDIM, DDIM);
    gemm_tf32_nt<<<ggrid, 256>>>(query, Wk, bk, nullptr, Km, ROWS, DDIM, DDIM);
    gemm_tf32_nt<<<ggrid, 256>>>(query, Wv, bv, nullptr, Vm, ROWS, DDIM, DDIM);

    // 3) logits + biases + mask  -> attn region
    dim3 lgrid(LLE/64, LLE/64, BB*HH);
    logits_kernel<<<lgrid, 256>>>(Qm, Km, pos_b, postag, lex, mask, attn);

    // 4) softmax in place
    softmax_kernel<<<BB*HH*LLE, 256>>>(attn);

    // 5) ctx = attn @ V
    dim3 agrid(LLE/64, BB*HH);
    av_kernel<<<agrid, 256>>>(attn, Vm, ctx);

    // 6) out = ctx @ Wo^T + bo + residual(query)
    gemm_tf32_nt<<<ggrid, 256>>>(ctx, Wo, bo, query, out, ROWS, DDIM, DDIM);
}

// round 4
// speedup vs baseline: 1.7498x; 1.2114x over previous
#include <cuda_runtime.h>
#include <math.h>

#define BB 2
#define LLE 1024
#define DDIM 1024
#define HH 16
#define DK 64
#define ROWS (BB*LLE)            // 2048
#define OUT_ELEMS (BB*LLE*DDIM)  // 2,097,152

// Scratch (allocation-free rule: __device__ globals)
__device__ float g_qn[ROWS*DDIM];
__device__ float g_q [ROWS*DDIM];
__device__ float g_k [ROWS*DDIM];
__device__ float g_v [ROWS*DDIM];
__device__ float g_ctx[ROWS*DDIM];

// ---------------------------------------------------------------------------
// helpers: tf32 convert + mma.m16n8k8 tf32
// ---------------------------------------------------------------------------
__device__ __forceinline__ unsigned tf32_bits(float x) {
    unsigned u;
    asm("cvt.rna.tf32.f32 %0, %1;" : "=r"(u) : "f"(x));
    return u;
}
__device__ __forceinline__ float tf32f(float x) { return __uint_as_float(tf32_bits(x)); }

__device__ __forceinline__ void mma_tf32(float acc[4], const unsigned a[4], const unsigned b[2]) {
    asm volatile(
        "mma.sync.aligned.m16n8k8.row.col.f32.tf32.tf32.f32 "
        "{%0,%1,%2,%3}, {%4,%5,%6,%7}, {%8,%9}, {%0,%1,%2,%3};"
        : "+f"(acc[0]), "+f"(acc[1]), "+f"(acc[2]), "+f"(acc[3])
        : "r"(a[0]), "r"(a[1]), "r"(a[2]), "r"(a[3]), "r"(b[0]), "r"(b[1]));
}

// ---------------------------------------------------------------------------
// LayerNorm
// ---------------------------------------------------------------------------
__global__ __launch_bounds__(256)
void ln_kernel(const float* __restrict__ x, const float* __restrict__ gamma,
               const float* __restrict__ beta, float* __restrict__ out)
{
    __shared__ float red[256];
    const int row = blockIdx.x;
    const int tid = threadIdx.x;
    float4 v = ((const float4*)(x + (size_t)row*DDIM))[tid];

    float s = v.x + v.y + v.z + v.w;
    red[tid] = s; __syncthreads();
    #pragma unroll
    for (int o = 128; o > 0; o >>= 1) { if (tid < o) red[tid] += red[tid+o]; __syncthreads(); }
    const float mean = red[0] * (1.0f/DDIM);
    __syncthreads();

    float dx0 = v.x-mean, dx1 = v.y-mean, dx2 = v.z-mean, dx3 = v.w-mean;
    float s2 = dx0*dx0 + dx1*dx1 + dx2*dx2 + dx3*dx3;
    red[tid] = s2; __syncthreads();
    #pragma unroll
    for (int o = 128; o > 0; o >>= 1) { if (tid < o) red[tid] += red[tid+o]; __syncthreads(); }
    const float var = red[0] * (1.0f/DDIM);
    const float rstd = rsqrtf(var + 1e-6f);

    float4 g = ((const float4*)gamma)[tid];
    float4 b = ((const float4*)beta )[tid];
    float4 o4;
    o4.x = dx0*rstd*g.x + b.x;
    o4.y = dx1*rstd*g.y + b.y;
    o4.z = dx2*rstd*g.z + b.z;
    o4.w = dx3*rstd*g.w + b.w;
    ((float4*)(out + (size_t)row*DDIM))[tid] = o4;
}

// ---------------------------------------------------------------------------
// tf32 tensor-core NT GEMM body (shared by qkv-combined and out-proj)
// ---------------------------------------------------------------------------
#define SSTR 20

__device__ __forceinline__
void gemm_body(const float* __restrict__ A, const float* __restrict__ W,
               const float* __restrict__ bias, const float* __restrict__ resid,
               float* __restrict__ C, int N, int K,
               float* As0, float* As1, float* Bs0, float* Bs1)
{
    float* AsArr[2] = {As0, As1};
    float* BsArr[2] = {Bs0, Bs1};

    const int tid  = threadIdx.x;
    const int lane = tid & 31;
    const int warp = tid >> 5;
    const int wm   = warp & 3;
    const int wn   = warp >> 2;
    const int gid  = lane >> 2;
    const int tig  = lane & 3;

    const int rowBase = blockIdx.y * 128;
    const int colBase = blockIdx.x * 128;

    const int lr = tid >> 2;
    const int lc = (tid & 3) * 4;
    const float* Ag = A + (size_t)(rowBase + lr) * K + lc;
    const float* Wg = W + (size_t)(colBase + lr) * K + lc;

    float acc[2][8][4];
    #pragma unroll
    for (int mt = 0; mt < 2; mt++)
        #pragma unroll
        for (int nt = 0; nt < 8; nt++)
            #pragma unroll
            for (int c = 0; c < 4; c++) acc[mt][nt][c] = 0.0f;

    float4 pa0, pa1, pb0, pb1;
    pa0 = *(const float4*)(Ag);
    pa1 = *(const float4*)(Ag + (size_t)64*K);
    pb0 = *(const float4*)(Wg);
    pb1 = *(const float4*)(Wg + (size_t)64*K);
    {
        float4 ca0 = {tf32f(pa0.x), tf32f(pa0.y), tf32f(pa0.z), tf32f(pa0.w)};
        float4 ca1 = {tf32f(pa1.x), tf32f(pa1.y), tf32f(pa1.z), tf32f(pa1.w)};
        float4 cb0 = {tf32f(pb0.x), tf32f(pb0.y), tf32f(pb0.z), tf32f(pb0.w)};
        float4 cb1 = {tf32f(pb1.x), tf32f(pb1.y), tf32f(pb1.z), tf32f(pb1.w)};
        *(float4*)&AsArr[0][lr*SSTR + lc] = ca0;
        *(float4*)&AsArr[0][(lr+64)*SSTR + lc] = ca1;
        *(float4*)&BsArr[0][lr*SSTR + lc] = cb0;
        *(float4*)&BsArr[0][(lr+64)*SSTR + lc] = cb1;
    }
    __syncthreads();

    int buf = 0;
    for (int k0 = 0; k0 < K; k0 += 16) {
        const bool hasNext = (k0 + 16) < K;
        if (hasNext) {
            pa0 = *(const float4*)(Ag + k0 + 16);
            pa1 = *(const float4*)(Ag + (size_t)64*K + k0 + 16);
            pb0 = *(const float4*)(Wg + k0 + 16);
            pb1 = *(const float4*)(Wg + (size_t)64*K + k0 + 16);
        }

        const float* Asb = AsArr[buf];
        const float* Bsb = BsArr[buf];
        #pragma unroll
        for (int ks = 0; ks < 16; ks += 8) {
            unsigned afr[2][4];
            #pragma unroll
            for (int mt = 0; mt < 2; mt++) {
                const float* ap = &Asb[(wm*32 + mt*16)*SSTR + ks];
                afr[mt][0] = __float_as_uint(ap[ gid     *SSTR + tig    ]);
                afr[mt][1] = __float_as_uint(ap[(gid + 8)*SSTR + tig    ]);
                afr[mt][2] = __float_as_uint(ap[ gid     *SSTR + tig + 4]);
                afr[mt][3] = __float_as_uint(ap[(gid + 8)*SSTR + tig + 4]);
            }
            unsigned bfr[8][2];
            #pragma unroll
            for (int nt = 0; nt < 8; nt++) {
                const float* bp = &Bsb[(wn*64 + nt*8)*SSTR + ks];
                bfr[nt][0] = __float_as_uint(bp[gid*SSTR + tig    ]);
                bfr[nt][1] = __float_as_uint(bp[gid*SSTR + tig + 4]);
            }
            #pragma unroll
            for (int mt = 0; mt < 2; mt++)
                #pragma unroll
                for (int nt = 0; nt < 8; nt++)
                    mma_tf32(acc[mt][nt], afr[mt], bfr[nt]);
        }

        if (hasNext) {
            const int nb = buf ^ 1;
            float4 ca0 = {tf32f(pa0.x), tf32f(pa0.y), tf32f(pa0.z), tf32f(pa0.w)};
            float4 ca1 = {tf32f(pa1.x), tf32f(pa1.y), tf32f(pa1.z), tf32f(pa1.w)};
            float4 cb0 = {tf32f(pb0.x), tf32f(pb0.y), tf32f(pb0.z), tf32f(pb0.w)};
            float4 cb1 = {tf32f(pb1.x), tf32f(pb1.y), tf32f(pb1.z), tf32f(pb1.w)};
            *(float4*)&AsArr[nb][lr*SSTR + lc] = ca0;
            *(float4*)&AsArr[nb][(lr+64)*SSTR + lc] = ca1;
            *(float4*)&BsArr[nb][lr*SSTR + lc] = cb0;
            *(float4*)&BsArr[nb][(lr+64)*SSTR + lc] = cb1;
            __syncthreads();
            buf = nb;
        }
    }

    #pragma unroll
    for (int nt = 0; nt < 8; nt++) {
        const int col = colBase + wn*64 + nt*8 + tig*2;
        float2 bz = *(const float2*)&bias[col];
        #pragma unroll
        for (int mt = 0; mt < 2; mt++) {
            const int r0 = rowBase + wm*32 + mt*16 + gid;
            const int r1 = r0 + 8;
            float2 v0 = { acc[mt][nt][0] + bz.x, acc[mt][nt][1] + bz.y };
            float2 v1 = { acc[mt][nt][2] + bz.x, acc[mt][nt][3] + bz.y };
            if (resid) {
                float2 q0 = *(const float2*)&resid[(size_t)r0*N + col];
                float2 q1 = *(const float2*)&resid[(size_t)r1*N + col];
                v0.x += q0.x; v0.y += q0.y;
                v1.x += q1.x; v1.y += q1.y;
            }
            *(float2*)&C[(size_t)r0*N + col] = v0;
            *(float2*)&C[(size_t)r1*N + col] = v1;
        }
    }
}

// combined Q/K/V projections: blockIdx.z selects which
__global__ __launch_bounds__(256)
void qkv_gemm(const float* __restrict__ qn, const float* __restrict__ query,
              const float* __restrict__ Wq, const float* __restrict__ Wk, const float* __restrict__ Wv,
              const float* __restrict__ bq, const float* __restrict__ bk, const float* __restrict__ bv,
              float* __restrict__ Qm, float* __restrict__ Km, float* __restrict__ Vm)
{
    __shared__ float As[2][128*SSTR];
    __shared__ float Bs[2][128*SSTR];
    const int z = blockIdx.z;
    const float* A = (z == 0) ? qn : query;
    const float* W = (z == 0) ? Wq : (z == 1) ? Wk : Wv;
    const float* b = (z == 0) ? bq : (z == 1) ? bk : bv;
    float* C       = (z == 0) ? Qm : (z == 1) ? Km : Vm;
    gemm_body(A, W, b, nullptr, C, DDIM, DDIM, As[0], As[1], Bs[0], Bs[1]);
}

__global__ __launch_bounds__(256)
void out_gemm(const float* __restrict__ A, const float* __restrict__ W,
              const float* __restrict__ bias, const float* __restrict__ resid,
              float* __restrict__ C)
{
    __shared__ float As[2][128*SSTR];
    __shared__ float Bs[2][128*SSTR];
    gemm_body(A, W, bias, resid, C, DDIM, DDIM, As[0], As[1], Bs[0], Bs[1]);
}

// ---------------------------------------------------------------------------
// Fused attention: logits (tf32 MMA) + biases + mask -> smem, softmax (MUFU),
// attn write (once), AV (tf32 MMA) -> ctx.
// q-tile = 16, 256 threads, 2 CTAs/SM.
// ---------------------------------------------------------------------------
#define QT 16
#define ST 128
#define S_STR 1036
#define K_STR 68
#define V_STR 133
#define SMO_K (QT*S_STR)                 // 16576 floats
#define SMO_Q (SMO_K + ST*K_STR)         // +8704 = 25280
#define SM_FLOATS (SMO_Q + QT*K_STR)     // +1088 = 26368
#define SM_BYTES (SM_FLOATS*4)           // 105472 B

__global__ void __launch_bounds__(256, 2)
attn_fused(const float* __restrict__ Qg, const float* __restrict__ Kg,
           const float* __restrict__ Vg,
           const float* __restrict__ pos_bias, const float* __restrict__ postag,
           const float* __restrict__ lex, const int* __restrict__ mask,
           float* __restrict__ attn, float* __restrict__ ctx)
{
    extern __shared__ float sm[];
    float* S  = sm;          // [QT][S_STR]
    float* Ks = sm + SMO_K;  // [ST][K_STR]   (QK phase)
    float* Vt = sm + SMO_K;  // [DK][V_STR]   (AV phase, union)
    float* Qs = sm + SMO_Q;  // [QT][K_STR]

    const int tid  = threadIdx.x;
    const int lane = tid & 31;
    const int w    = tid >> 5;
    const int gid  = lane >> 2;
    const int tig  = lane & 3;
    const int qBase = blockIdx.x * QT;
    const int bh = blockIdx.y;
    const int b = bh >> 4, h = bh & 15;

    // ---- load Q tile (16 x 64), tf32 ----
    {
        const int r = tid >> 4;
        const int c = (tid & 15) * 4;
        float4 v = *(const float4*)&Qg[((size_t)(b*LLE + qBase + r))*DDIM + h*DK + c];
        float4 cv = {tf32f(v.x), tf32f(v.y), tf32f(v.z), tf32f(v.w)};
        *(float4*)&Qs[r*K_STR + c] = cv;
    }

    // ---- QK phase ----
    for (int s0 = 0; s0 < LLE; s0 += ST) {
        __syncthreads();   // prev Ks reads done (and Qs visible on first iter)
        #pragma unroll
        for (int t = 0; t < 8; t++) {
            const int idx = tid + t*256;       // 0..2047
            const int r = idx >> 4;
            const int c = (idx & 15) * 4;
            float4 v = *(const float4*)&Kg[((size_t)(b*LLE + s0 + r))*DDIM + h*DK + c];
            float4 cv = {tf32f(v.x), tf32f(v.y), tf32f(v.z), tf32f(v.w)};
            *(float4*)&Ks[r*K_STR + c] = cv;
        }
        __syncthreads();

        // warp w handles s-cols [w*16, w*16+16)
        float acc[2][4];
        #pragma unroll
        for (int nt = 0; nt < 2; nt++)
            #pragma unroll
            for (int c = 0; c < 4; c++) acc[nt][c] = 0.0f;

        #pragma unroll
        for (int ks = 0; ks < DK; ks += 8) {
            unsigned a[4];
            a[0] = __float_as_uint(Qs[ gid     *K_STR + ks + tig    ]);
            a[1] = __float_as_uint(Qs[(gid + 8)*K_STR + ks + tig    ]);
            a[2] = __float_as_uint(Qs[ gid     *K_STR + ks + tig + 4]);
            a[3] = __float_as_uint(Qs[(gid + 8)*K_STR + ks + tig + 4]);
            #pragma unroll
            for (int nt = 0; nt < 2; nt++) {
                const float* bp = &Ks[(w*16 + nt*8)*K_STR + ks];
                unsigned bf[2];
                bf[0] = __float_as_uint(bp[gid*K_STR + tig    ]);
                bf[1] = __float_as_uint(bp[gid*K_STR + tig + 4]);
                mma_tf32(acc[nt], a, bf);
            }
        }

        // epilogue: scale + biases + mask -> S
        #pragma unroll
        for (int nt = 0; nt < 2; nt++) {
            const int cc = w*16 + nt*8 + tig*2;
            const int sg = s0 + cc;
            float2 lx = *(const float2*)&lex [b*LLE + sg];
            int2   mk = *(const int2 *)&mask[b*LLE + sg];
            const int r0 = qBase + gid;
            const int r1 = r0 + 8;
            float2 pb0 = *(const float2*)&pos_bias[((size_t)h*LLE + r0)*LLE + sg];
            float2 pb1 = *(const float2*)&pos_bias[((size_t)h*LLE + r1)*LLE + sg];
            float2 pt0 = *(const float2*)&postag  [((size_t)bh*LLE + r0)*LLE + sg];
            float2 pt1 = *(const float2*)&postag  [((size_t)bh*LLE + r1)*LLE + sg];
            float2 v0, v1;
            v0.x = (mk.x == 0) ? -1e30f : (acc[nt][0]*0.125f + pb0.x + pt0.x + lx.x);
            v0.y = (mk.y == 0) ? -1e30f : (acc[nt][1]*0.125f + pb0.y + pt0.y + lx.y);
            v1.x = (mk.x == 0) ? -1e30f : (acc[nt][2]*0.125f + pb1.x + pt1.x + lx.x);
            v1.y = (mk.y == 0) ? -1e30f : (acc[nt][3]*0.125f + pb1.y + pt1.y + lx.y);
            *(float2*)&S[ gid     *S_STR + sg] = v0;
            *(float2*)&S[(gid + 8)*S_STR + sg] = v1;
        }
    }
    __syncthreads();

    // ---- softmax: warp w handles rows 2w, 2w+1 ----
    #pragma unroll
    for (int rr = 0; rr < 2; rr++) {
        const int r = w*2 + rr;
        float4 vals[8];
        float m = -3.4e38f;
        #pragma unroll
        for (int i = 0; i < 8; i++) {
            vals[i] = *(const float4*)&S[r*S_STR + (i*32 + lane)*4];
            m = fmaxf(m, fmaxf(fmaxf(vals[i].x, vals[i].y), fmaxf(vals[i].z, vals[i].w)));
        }
        #pragma unroll
        for (int o = 16; o > 0; o >>= 1) m = fmaxf(m, __shfl_xor_sync(0xffffffffu, m, o));

        float sum = 0.0f;
        #pragma unroll
        for (int i = 0; i < 8; i++) {
            vals[i].x = __expf(vals[i].x - m);
            vals[i].y = __expf(vals[i].y - m);
            vals[i].z = __expf(vals[i].z - m);
            vals[i].w = __expf(vals[i].w - m);
            sum += vals[i].x + vals[i].y + vals[i].z + vals[i].w;
        }
        #pragma unroll
        for (int o = 16; o > 0; o >>= 1) sum += __shfl_xor_sync(0xffffffffu, sum, o);
        const float inv = 1.0f / sum;

        float* arow = &attn[((size_t)bh*LLE + qBase + r)*LLE];
        #pragma unroll
        for (int i = 0; i < 8; i++) {
            float4 p;
            p.x = vals[i].x * inv; p.y = vals[i].y * inv;
            p.z = vals[i].z * inv; p.w = vals[i].w * inv;
            *(float4*)&arow[(i*32 + lane)*4] = p;                // exact fp32 attn
            float4 pt = {tf32f(p.x), tf32f(p.y), tf32f(p.z), tf32f(p.w)};
            *(float4*)&S[r*S_STR + (i*32 + lane)*4] = pt;        // tf32 for AV
        }
    }

    // ---- AV phase: warp w handles out cols [w*8, w*8+8) ----
    float av[4] = {0.0f, 0.0f, 0.0f, 0.0f};
    for (int s0 = 0; s0 < LLE; s0 += ST) {
        __syncthreads();   // softmax done / prev Vt reads done
        #pragma unroll
        for (int t = 0; t < 8; t++) {
            const int idx = tid + t*256;       // 0..2047
            const int k = idx >> 4;            // 0..127 (s within tile)
            const int n = (idx & 15) * 4;
            float4 v = *(const float4*)&Vg[((size_t)(b*LLE + s0 + k))*DDIM + h*DK + n];
            Vt[(n+0)*V_STR + k] = tf32f(v.x);
            Vt[(n+1)*V_STR + k] = tf32f(v.y);
            Vt[(n+2)*V_STR + k] = tf32f(v.z);
            Vt[(n+3)*V_STR + k] = tf32f(v.w);
        }
        __syncthreads();

        #pragma unroll
        for (int ks = 0; ks < ST; ks += 8) {
            const int kk = s0 + ks;
            unsigned a[4];
            a[0] = __float_as_uint(S[ gid     *S_STR + kk + tig    ]);
            a[1] = __float_as_uint(S[(gid + 8)*S_STR + kk + tig    ]);
            a[2] = __float_as_uint(S[ gid     *S_STR + kk + tig + 4]);
            a[3] = __float_as_uint(S[(gid + 8)*S_STR + kk + tig + 4]);
            const float* bp = &Vt[(w*8)*V_STR + ks];
            unsigned bf[2];
            bf[0] = __float_as_uint(bp[gid*V_STR + tig    ]);
            bf[1] = __float_as_uint(bp[gid*V_STR + tig + 4]);
            mma_tf32(av, a, bf);
        }
    }

    // write ctx
    {
        const int cc = h*DK + w*8 + tig*2;
        const int r0 = b*LLE + qBase + gid;
        float2 o0 = {av[0], av[1]};
        float2 o1 = {av[2], av[3]};
        *(float2*)&ctx[(size_t)r0*DDIM + cc] = o0;
        *(float2*)&ctx[(size_t)(r0+8)*DDIM + cc] = o1;
    }
}

// ---------------------------------------------------------------------------
extern "C" void kernel_launch(void* const* d_in, const int* in_sizes, int n_in,
                              void* d_out, int out_size)
{
    const float* query  = (const float*)d_in[0];
    const float* pos_b  = (const float*)d_in[1];
    const float* postag = (const float*)d_in[2];
    const float* lex    = (const float*)d_in[3];
    const int*   mask   = (const int*  )d_in[4];
    const float* Wq = (const float*)d_in[5];
    const float* bq = (const float*)d_in[6];
    const float* Wk = (const float*)d_in[7];
    const float* bk = (const float*)d_in[8];
    const float* Wv = (const float*)d_in[9];
    const float* bv = (const float*)d_in[10];
    const float* Wo = (const float*)d_in[11];
    const float* bo = (const float*)d_in[12];
    const float* gamma = (const float*)d_in[13];
    const float* beta  = (const float*)d_in[14];

    float* out  = (float*)d_out;             // (B,L,D)
    float* attn = (float*)d_out + OUT_ELEMS; // (B,H,L,L)

    float* qn  = nullptr; cudaGetSymbolAddress((void**)&qn,  g_qn);
    float* Qm  = nullptr; cudaGetSymbolAddress((void**)&Qm,  g_q);
    float* Km  = nullptr; cudaGetSymbolAddress((void**)&Km,  g_k);
    float* Vm  = nullptr; cudaGetSymbolAddress((void**)&Vm,  g_v);
    float* ctx = nullptr; cudaGetSymbolAddress((void**)&ctx, g_ctx);

    static bool attrSet = false;
    if (!attrSet) {
        cudaFuncSetAttribute(attn_fused, cudaFuncAttributeMaxDynamicSharedMemorySize, SM_BYTES);
        attrSet = true;
    }

    // 1) pre-LN on query only
    ln_kernel<<<ROWS, 256>>>(query, gamma, beta, qn);

    // 2) Q/K/V projections in one launch (384 CTAs)
    dim3 qkvGrid(DDIM/128, ROWS/128, 3);
    qkv_gemm<<<qkvGrid, 256>>>(qn, query, Wq, Wk, Wv, bq, bk, bv, Qm, Km, Vm);

    // 3) fused logits + softmax + AV
    dim3 aGrid(LLE/QT, BB*HH);
    attn_fused<<<aGrid, 256, SM_BYTES>>>(Qm, Km, Vm, pos_b, postag, lex, mask, attn, ctx);

    // 4) out = ctx @ Wo^T + bo + residual(query)
    dim3 oGrid(DDIM/128, ROWS/128);
    out_gemm<<<oGrid, 256>>>(ctx, Wo, bo, query, out);
}

// round 5
// speedup vs baseline: 2.4073x; 1.3758x over previous
#include <cuda_runtime.h>
#include <math.h>

#define BB 2
#define LLE 1024
#define DDIM 1024
#define HH 16
#define DK 64
#define ROWS (BB*LLE)            // 2048
#define OUT_ELEMS (BB*LLE*DDIM)  // 2,097,152

// Scratch (allocation-free rule: __device__ globals)
__device__ float g_qn[ROWS*DDIM];
__device__ float g_q [ROWS*DDIM];
__device__ float g_k [ROWS*DDIM];
__device__ float g_v [ROWS*DDIM];
__device__ float g_ctx[ROWS*DDIM];

// ---------------------------------------------------------------------------
// helpers
// ---------------------------------------------------------------------------
__device__ __forceinline__ unsigned tf32_bits(float x) {
    unsigned u;
    asm("cvt.rna.tf32.f32 %0, %1;" : "=r"(u) : "f"(x));
    return u;
}
__device__ __forceinline__ float tf32f(float x) { return __uint_as_float(tf32_bits(x)); }

__device__ __forceinline__ void mma_tf32(float acc[4], const unsigned a[4], const unsigned b[2]) {
    asm volatile(
        "mma.sync.aligned.m16n8k8.row.col.f32.tf32.tf32.f32 "
        "{%0,%1,%2,%3}, {%4,%5,%6,%7}, {%8,%9}, {%0,%1,%2,%3};"
        : "+f"(acc[0]), "+f"(acc[1]), "+f"(acc[2]), "+f"(acc[3])
        : "r"(a[0]), "r"(a[1]), "r"(a[2]), "r"(a[3]), "r"(b[0]), "r"(b[1]));
}

// FMA-pipe exp(x) for x<=0 via 2^t decomposition, no MUFU. t = x*log2e.
__device__ __forceinline__ float exp_poly_t(float t) {
    t = fmaxf(t, -126.0f);
    const float MAGIC = 12582912.0f;       // 2^23 * 1.5
    float z = t + MAGIC;
    int   i = __float_as_int(z);
    float r = t - (z - MAGIC);             // r in [-0.5, 0.5]
    // 2^r, degree-5, rel err ~2e-8
    float p = 0.00133335581f;
    p = fmaf(p, r, 0.00961804886f);
    p = fmaf(p, r, 0.0555041086f);
    p = fmaf(p, r, 0.240226507f);
    p = fmaf(p, r, 0.693147182f);
    p = fmaf(p, r, 1.0f);
    float s = __int_as_float((i - 0x4B400000 + 127) << 23);
    return p * s;
}

// ---------------------------------------------------------------------------
// LayerNorm
// ---------------------------------------------------------------------------
__global__ __launch_bounds__(256)
void ln_kernel(const float* __restrict__ x, const float* __restrict__ gamma,
               const float* __restrict__ beta, float* __restrict__ out)
{
    __shared__ float red[256];
    const int row = blockIdx.x;
    const int tid = threadIdx.x;
    float4 v = ((const float4*)(x + (size_t)row*DDIM))[tid];

    float s = v.x + v.y + v.z + v.w;
    red[tid] = s; __syncthreads();
    #pragma unroll
    for (int o = 128; o > 0; o >>= 1) { if (tid < o) red[tid] += red[tid+o]; __syncthreads(); }
    const float mean = red[0] * (1.0f/DDIM);
    __syncthreads();

    float dx0 = v.x-mean, dx1 = v.y-mean, dx2 = v.z-mean, dx3 = v.w-mean;
    float s2 = dx0*dx0 + dx1*dx1 + dx2*dx2 + dx3*dx3;
    red[tid] = s2; __syncthreads();
    #pragma unroll
    for (int o = 128; o > 0; o >>= 1) { if (tid < o) red[tid] += red[tid+o]; __syncthreads(); }
    const float var = red[0] * (1.0f/DDIM);
    const float rstd = rsqrtf(var + 1e-6f);

    float4 g = ((const float4*)gamma)[tid];
    float4 b = ((const float4*)beta )[tid];
    float4 o4;
    o4.x = dx0*rstd*g.x + b.x;
    o4.y = dx1*rstd*g.y + b.y;
    o4.z = dx2*rstd*g.z + b.z;
    o4.w = dx3*rstd*g.w + b.w;
    ((float4*)(out + (size_t)row*DDIM))[tid] = o4;
}

// ---------------------------------------------------------------------------
// tf32 tensor-core NT GEMM body: 64x128 block tile, k-step 16, double buffer.
// 8 warps, warp tile 32x32. Optionally rounds the output to tf32 (for Q/K/V).
// ---------------------------------------------------------------------------
#define SSTR 20

__device__ __forceinline__
void gemm_body(const float* __restrict__ A, const float* __restrict__ W,
               const float* __restrict__ bias, const float* __restrict__ resid,
               float* __restrict__ C, int N, int K, int roundOut,
               float* As0, float* As1, float* Bs0, float* Bs1)
{
    float* AsArr[2] = {As0, As1};
    float* BsArr[2] = {Bs0, Bs1};

    const int tid  = threadIdx.x;
    const int lane = tid & 31;
    const int warp = tid >> 5;
    const int wm   = warp >> 2;  // 0..1 : 32-row slab
    const int wn   = warp & 3;   // 0..3 : 32-col slab
    const int gid  = lane >> 2;
    const int tig  = lane & 3;

    const int rowBase = blockIdx.y * 64;
    const int colBase = blockIdx.x * 128;

    const int lr = tid >> 2;          // 0..63
    const int lc = (tid & 3) * 4;     // 0,4,8,12
    const float* Ag = A + (size_t)(rowBase + lr) * K + lc;
    const float* Wg = W + (size_t)(colBase + lr) * K + lc;

    float acc[2][4][4];
    #pragma unroll
    for (int mt = 0; mt < 2; mt++)
        #pragma unroll
        for (int nt = 0; nt < 4; nt++)
            #pragma unroll
            for (int c = 0; c < 4; c++) acc[mt][nt][c] = 0.0f;

    float4 pa0, pb0, pb1;
    pa0 = *(const float4*)(Ag);
    pb0 = *(const float4*)(Wg);
    pb1 = *(const float4*)(Wg + (size_t)64*K);
    {
        float4 ca0 = {tf32f(pa0.x), tf32f(pa0.y), tf32f(pa0.z), tf32f(pa0.w)};
        float4 cb0 = {tf32f(pb0.x), tf32f(pb0.y), tf32f(pb0.z), tf32f(pb0.w)};
        float4 cb1 = {tf32f(pb1.x), tf32f(pb1.y), tf32f(pb1.z), tf32f(pb1.w)};
        *(float4*)&AsArr[0][lr*SSTR + lc] = ca0;
        *(float4*)&BsArr[0][lr*SSTR + lc] = cb0;
        *(float4*)&BsArr[0][(lr+64)*SSTR + lc] = cb1;
    }
    __syncthreads();

    int buf = 0;
    for (int k0 = 0; k0 < K; k0 += 16) {
        const bool hasNext = (k0 + 16) < K;
        if (hasNext) {
            pa0 = *(const float4*)(Ag + k0 + 16);
            pb0 = *(const float4*)(Wg + k0 + 16);
            pb1 = *(const float4*)(Wg + (size_t)64*K + k0 + 16);
        }

        const float* Asb = AsArr[buf];
        const float* Bsb = BsArr[buf];
        #pragma unroll
        for (int ks = 0; ks < 16; ks += 8) {
            unsigned afr[2][4];
            #pragma unroll
            for (int mt = 0; mt < 2; mt++) {
                const float* ap = &Asb[(wm*32 + mt*16)*SSTR + ks];
                afr[mt][0] = __float_as_uint(ap[ gid     *SSTR + tig    ]);
                afr[mt][1] = __float_as_uint(ap[(gid + 8)*SSTR + tig    ]);
                afr[mt][2] = __float_as_uint(ap[ gid     *SSTR + tig + 4]);
                afr[mt][3] = __float_as_uint(ap[(gid + 8)*SSTR + tig + 4]);
            }
            unsigned bfr[4][2];
            #pragma unroll
            for (int nt = 0; nt < 4; nt++) {
                const float* bp = &Bsb[(wn*32 + nt*8)*SSTR + ks];
                bfr[nt][0] = __float_as_uint(bp[gid*SSTR + tig    ]);
                bfr[nt][1] = __float_as_uint(bp[gid*SSTR + tig + 4]);
            }
            #pragma unroll
            for (int mt = 0; mt < 2; mt++)
                #pragma unroll
                for (int nt = 0; nt < 4; nt++)
                    mma_tf32(acc[mt][nt], afr[mt], bfr[nt]);
        }

        if (hasNext) {
            const int nb = buf ^ 1;
            float4 ca0 = {tf32f(pa0.x), tf32f(pa0.y), tf32f(pa0.z), tf32f(pa0.w)};
            float4 cb0 = {tf32f(pb0.x), tf32f(pb0.y), tf32f(pb0.z), tf32f(pb0.w)};
            float4 cb1 = {tf32f(pb1.x), tf32f(pb1.y), tf32f(pb1.z), tf32f(pb1.w)};
            *(float4*)&AsArr[nb][lr*SSTR + lc] = ca0;
            *(float4*)&BsArr[nb][lr*SSTR + lc] = cb0;
            *(float4*)&BsArr[nb][(lr+64)*SSTR + lc] = cb1;
            __syncthreads();
            buf = nb;
        }
    }

    #pragma unroll
    for (int nt = 0; nt < 4; nt++) {
        const int col = colBase + wn*32 + nt*8 + tig*2;
        float2 bz = *(const float2*)&bias[col];
        #pragma unroll
        for (int mt = 0; mt < 2; mt++) {
            const int r0 = rowBase + wm*32 + mt*16 + gid;
            const int r1 = r0 + 8;
            float2 v0 = { acc[mt][nt][0] + bz.x, acc[mt][nt][1] + bz.y };
            float2 v1 = { acc[mt][nt][2] + bz.x, acc[mt][nt][3] + bz.y };
            if (resid) {
                float2 q0 = *(const float2*)&resid[(size_t)r0*N + col];
                float2 q1 = *(const float2*)&resid[(size_t)r1*N + col];
                v0.x += q0.x; v0.y += q0.y;
                v1.x += q1.x; v1.y += q1.y;
            }
            if (roundOut) {
                v0.x = tf32f(v0.x); v0.y = tf32f(v0.y);
                v1.x = tf32f(v1.x); v1.y = tf32f(v1.y);
            }
            *(float2*)&C[(size_t)r0*N + col] = v0;
            *(float2*)&C[(size_t)r1*N + col] = v1;
        }
    }
}

// combined Q/K/V projections: blockIdx.z selects which; outputs pre-rounded tf32
__global__ __launch_bounds__(256)
void qkv_gemm(const float* __restrict__ qn, const float* __restrict__ query,
              const float* __restrict__ Wq, const float* __restrict__ Wk, const float* __restrict__ Wv,
              const float* __restrict__ bq, const float* __restrict__ bk, const float* __restrict__ bv,
              float* __restrict__ Qm, float* __restrict__ Km, float* __restrict__ Vm)
{
    __shared__ float As[2][64*SSTR];
    __shared__ float Bs[2][128*SSTR];
    const int z = blockIdx.z;
    const float* A = (z == 0) ? qn : query;
    const float* W = (z == 0) ? Wq : (z == 1) ? Wk : Wv;
    const float* b = (z == 0) ? bq : (z == 1) ? bk : bv;
    float* C       = (z == 0) ? Qm : (z == 1) ? Km : Vm;
    gemm_body(A, W, b, nullptr, C, DDIM, DDIM, 1, As[0], As[1], Bs[0], Bs[1]);
}

__global__ __launch_bounds__(256)
void out_gemm(const float* __restrict__ A, const float* __restrict__ W,
              const float* __restrict__ bias, const float* __restrict__ resid,
              float* __restrict__ C)
{
    __shared__ float As[2][64*SSTR];
    __shared__ float Bs[2][128*SSTR];
    gemm_body(A, W, bias, resid, C, DDIM, DDIM, 0, As[0], As[1], Bs[0], Bs[1]);
}

// ---------------------------------------------------------------------------
// Fused attention: logits (tf32 MMA) + biases + mask -> smem, softmax (hybrid
// MUFU + FMA-poly exp), attn write (once), AV (tf32 MMA) -> ctx.
// q-tile = 16, 256 threads, 2 CTAs/SM. Q/K/V arrive pre-rounded to tf32.
// ---------------------------------------------------------------------------
#define QT 16
#define ST 128
#define S_STR 1036
#define K_STR 68
#define V_STR 133
#define SMO_K (QT*S_STR)                 // 16576 floats
#define SMO_Q (SMO_K + ST*K_STR)         // +8704 = 25280
#define SM_FLOATS (SMO_Q + QT*K_STR)     // +1088 = 26368
#define SM_BYTES (SM_FLOATS*4)           // 105472 B

__global__ void __launch_bounds__(256, 2)
attn_fused(const float* __restrict__ Qg, const float* __restrict__ Kg,
           const float* __restrict__ Vg,
           const float* __restrict__ pos_bias, const float* __restrict__ postag,
           const float* __restrict__ lex, const int* __restrict__ mask,
           float* __restrict__ attn, float* __restrict__ ctx)
{
    extern __shared__ float sm[];
    float* S  = sm;          // [QT][S_STR]
    float* Ks = sm + SMO_K;  // [ST][K_STR]   (QK phase)
    float* Vt = sm + SMO_K;  // [DK][V_STR]   (AV phase, union)
    float* Qs = sm + SMO_Q;  // [QT][K_STR]

    const int tid  = threadIdx.x;
    const int lane = tid & 31;
    const int w    = tid >> 5;
    const int gid  = lane >> 2;
    const int tig  = lane & 3;
    const int qBase = blockIdx.x * QT;
    const int bh = blockIdx.y;
    const int b = bh >> 4, h = bh & 15;

    // ---- load Q tile (16 x 64), already tf32 ----
    {
        const int r = tid >> 4;
        const int c = (tid & 15) * 4;
        float4 v = *(const float4*)&Qg[((size_t)(b*LLE + qBase + r))*DDIM + h*DK + c];
        *(float4*)&Qs[r*K_STR + c] = v;
    }

    // ---- QK phase ----
    for (int s0 = 0; s0 < LLE; s0 += ST) {
        __syncthreads();   // prev Ks reads done (and Qs visible on first iter)
        #pragma unroll
        for (int t = 0; t < 8; t++) {
            const int idx = tid + t*256;       // 0..2047
            const int r = idx >> 4;
            const int c = (idx & 15) * 4;
            float4 v = *(const float4*)&Kg[((size_t)(b*LLE + s0 + r))*DDIM + h*DK + c];
            *(float4*)&Ks[r*K_STR + c] = v;
        }

        // prefetch epilogue operands (consumed after MMA -> latency hidden)
        float2 lx[2], pb0[2], pb1[2], pt0[2], pt1[2];
        int2 mk[2];
        #pragma unroll
        for (int nt = 0; nt < 2; nt++) {
            const int cc = w*16 + nt*8 + tig*2;
            const int sg = s0 + cc;
            lx[nt] = *(const float2*)&lex [b*LLE + sg];
            mk[nt] = *(const int2 *)&mask[b*LLE + sg];
            const int r0 = qBase + gid;
            const int r1 = r0 + 8;
            pb0[nt] = *(const float2*)&pos_bias[((size_t)h*LLE + r0)*LLE + sg];
            pb1[nt] = *(const float2*)&pos_bias[((size_t)h*LLE + r1)*LLE + sg];
            pt0[nt] = *(const float2*)&postag  [((size_t)bh*LLE + r0)*LLE + sg];
            pt1[nt] = *(const float2*)&postag  [((size_t)bh*LLE + r1)*LLE + sg];
        }
        __syncthreads();

        // warp w handles s-cols [w*16, w*16+16)
        float acc[2][4];
        #pragma unroll
        for (int nt = 0; nt < 2; nt++)
            #pragma unroll
            for (int c = 0; c < 4; c++) acc[nt][c] = 0.0f;

        #pragma unroll
        for (int ks = 0; ks < DK; ks += 8) {
            unsigned a[4];
            a[0] = __float_as_uint(Qs[ gid     *K_STR + ks + tig    ]);
            a[1] = __float_as_uint(Qs[(gid + 8)*K_STR + ks + tig    ]);
            a[2] = __float_as_uint(Qs[ gid     *K_STR + ks + tig + 4]);
            a[3] = __float_as_uint(Qs[(gid + 8)*K_STR + ks + tig + 4]);
            #pragma unroll
            for (int nt = 0; nt < 2; nt++) {
                const float* bp = &Ks[(w*16 + nt*8)*K_STR + ks];
                unsigned bf[2];
                bf[0] = __float_as_uint(bp[gid*K_STR + tig    ]);
                bf[1] = __float_as_uint(bp[gid*K_STR + tig + 4]);
                mma_tf32(acc[nt], a, bf);
            }
        }

        // epilogue: scale + biases + mask -> S
        #pragma unroll
        for (int nt = 0; nt < 2; nt++) {
            const int cc = w*16 + nt*8 + tig*2;
            const int sg = s0 + cc;
            float2 v0, v1;
            v0.x = (mk[nt].x == 0) ? -1e30f : (acc[nt][0]*0.125f + pb0[nt].x + pt0[nt].x + lx[nt].x);
            v0.y = (mk[nt].y == 0) ? -1e30f : (acc[nt][1]*0.125f + pb0[nt].y + pt0[nt].y + lx[nt].y);
            v1.x = (mk[nt].x == 0) ? -1e30f : (acc[nt][2]*0.125f + pb1[nt].x + pt1[nt].x + lx[nt].x);
            v1.y = (mk[nt].y == 0) ? -1e30f : (acc[nt][3]*0.125f + pb1[nt].y + pt1[nt].y + lx[nt].y);
            *(float2*)&S[ gid     *S_STR + sg] = v0;
            *(float2*)&S[(gid + 8)*S_STR + sg] = v1;
        }
    }
    __syncthreads();

    // ---- softmax: warp w handles rows 2w, 2w+1; hybrid MUFU/poly exp ----
    #pragma unroll
    for (int rr = 0; rr < 2; rr++) {
        const int r = w*2 + rr;
        float4 vals[8];
        float m = -3.4e38f;
        #pragma unroll
        for (int i = 0; i < 8; i++) {
            vals[i] = *(const float4*)&S[r*S_STR + (i*32 + lane)*4];
            m = fmaxf(m, fmaxf(fmaxf(vals[i].x, vals[i].y), fmaxf(vals[i].z, vals[i].w)));
        }
        #pragma unroll
        for (int o = 16; o > 0; o >>= 1) m = fmaxf(m, __shfl_xor_sync(0xffffffffu, m, o));

        const float LOG2E = 1.4426950408889634f;
        const float mLog = m * LOG2E;

        float sum = 0.0f;
        #pragma unroll
        for (int i = 0; i < 8; i++) {
            if ((i & 3) == 3) {
                // FMA-pipe path (25% of elements): exp(v-m) = 2^(v*log2e - mLog)
                vals[i].x = exp_poly_t(fmaf(vals[i].x, LOG2E, -mLog));
                vals[i].y = exp_poly_t(fmaf(vals[i].y, LOG2E, -mLog));
                vals[i].z = exp_poly_t(fmaf(vals[i].z, LOG2E, -mLog));
                vals[i].w = exp_poly_t(fmaf(vals[i].w, LOG2E, -mLog));
            } else {
                vals[i].x = __expf(vals[i].x - m);
                vals[i].y = __expf(vals[i].y - m);
                vals[i].z = __expf(vals[i].z - m);
                vals[i].w = __expf(vals[i].w - m);
            }
            sum += vals[i].x + vals[i].y + vals[i].z + vals[i].w;
        }
        #pragma unroll
        for (int o = 16; o > 0; o >>= 1) sum += __shfl_xor_sync(0xffffffffu, sum, o);
        const float inv = 1.0f / sum;

        float* arow = &attn[((size_t)bh*LLE + qBase + r)*LLE];
        #pragma unroll
        for (int i = 0; i < 8; i++) {
            float4 p;
            p.x = vals[i].x * inv; p.y = vals[i].y * inv;
            p.z = vals[i].z * inv; p.w = vals[i].w * inv;
            *(float4*)&arow[(i*32 + lane)*4] = p;                // exact fp32 attn
            float4 pt = {tf32f(p.x), tf32f(p.y), tf32f(p.z), tf32f(p.w)};
            *(float4*)&S[r*S_STR + (i*32 + lane)*4] = pt;        // tf32 for AV
        }
    }

    // ---- AV phase: warp w handles out cols [w*8, w*8+8) ----
    float av[4] = {0.0f, 0.0f, 0.0f, 0.0f};
    for (int s0 = 0; s0 < LLE; s0 += ST) {
        __syncthreads();   // softmax done / prev Vt reads done
        #pragma unroll
        for (int t = 0; t < 8; t++) {
            const int idx = tid + t*256;       // 0..2047
            const int k = idx >> 4;            // 0..127 (s within tile)
            const int n = (idx & 15) * 4;
            float4 v = *(const float4*)&Vg[((size_t)(b*LLE + s0 + k))*DDIM + h*DK + n];
            Vt[(n+0)*V_STR + k] = v.x;
            Vt[(n+1)*V_STR + k] = v.y;
            Vt[(n+2)*V_STR + k] = v.z;
            Vt[(n+3)*V_STR + k] = v.w;
        }
        __syncthreads();

        #pragma unroll
        for (int ks = 0; ks < ST; ks += 8) {
            const int kk = s0 + ks;
            unsigned a[4];
            a[0] = __float_as_uint(S[ gid     *S_STR + kk + tig    ]);
            a[1] = __float_as_uint(S[(gid + 8)*S_STR + kk + tig    ]);
            a[2] = __float_as_uint(S[ gid     *S_STR + kk + tig + 4]);
            a[3] = __float_as_uint(S[(gid + 8)*S_STR + kk + tig + 4]);
            const float* bp = &Vt[(w*8)*V_STR + ks];
            unsigned bf[2];
            bf[0] = __float_as_uint(bp[gid*V_STR + tig    ]);
            bf[1] = __float_as_uint(bp[gid*V_STR + tig + 4]);
            mma_tf32(av, a, bf);
        }
    }

    // write ctx
    {
        const int cc = h*DK + w*8 + tig*2;
        const int r0 = b*LLE + qBase + gid;
        float2 o0 = {av[0], av[1]};
        float2 o1 = {av[2], av[3]};
        *(float2*)&ctx[(size_t)r0*DDIM + cc] = o0;
        *(float2*)&ctx[(size_t)(r0+8)*DDIM + cc] = o1;
    }
}

// ---------------------------------------------------------------------------
extern "C" void kernel_launch(void* const* d_in, const int* in_sizes, int n_in,
                              void* d_out, int out_size)
{
    const float* query  = (const float*)d_in[0];
    const float* pos_b  = (const float*)d_in[1];
    const float* postag = (const float*)d_in[2];
    const float* lex    = (const float*)d_in[3];
    const int*   mask   = (const int*  )d_in[4];
    const float* Wq = (const float*)d_in[5];
    const float* bq = (const float*)d_in[6];
    const float* Wk = (const float*)d_in[7];
    const float* bk = (const float*)d_in[8];
    const float* Wv = (const float*)d_in[9];
    const float* bv = (const float*)d_in[10];
    const float* Wo = (const float*)d_in[11];
    const float* bo = (const float*)d_in[12];
    const float* gamma = (const float*)d_in[13];
    const float* beta  = (const float*)d_in[14];

    float* out  = (float*)d_out;             // (B,L,D)
    float* attn = (float*)d_out + OUT_ELEMS; // (B,H,L,L)

    float* qn  = nullptr; cudaGetSymbolAddress((void**)&qn,  g_qn);
    float* Qm  = nullptr; cudaGetSymbolAddress((void**)&Qm,  g_q);
    float* Km  = nullptr; cudaGetSymbolAddress((void**)&Km,  g_k);
    float* Vm  = nullptr; cudaGetSymbolAddress((void**)&Vm,  g_v);
    float* ctx = nullptr; cudaGetSymbolAddress((void**)&ctx, g_ctx);

    cudaFuncSetAttribute(attn_fused, cudaFuncAttributeMaxDynamicSharedMemorySize, SM_BYTES);

    // 1) pre-LN on query only
    ln_kernel<<<ROWS, 256>>>(query, gamma, beta, qn);

    // 2) Q/K/V projections in one launch (768 CTAs), outputs pre-rounded tf32
    dim3 qkvGrid(DDIM/128, ROWS/64, 3);
    qkv_gemm<<<qkvGrid, 256>>>(qn, query, Wq, Wk, Wv, bq, bk, bv, Qm, Km, Vm);

    // 3) fused logits + softmax + AV
    dim3 aGrid(LLE/QT, BB*HH);
    attn_fused<<<aGrid, 256, SM_BYTES>>>(Qm, Km, Vm, pos_b, postag, lex, mask, attn, ctx);

    // 4) out = ctx @ Wo^T + bo + residual(query)
    dim3 oGrid(DDIM/128, ROWS/64);
    out_gemm<<<oGrid, 256>>>(ctx, Wo, bo, query, out);
}

// round 6
// speedup vs baseline: 2.7070x; 1.1245x over previous
#include <cuda_runtime.h>
#include <math.h>

#define BB 2
#define LLE 1024
#define DDIM 1024
#define HH 16
#define DK 64
#define ROWS (BB*LLE)            // 2048
#define OUT_ELEMS (BB*LLE*DDIM)  // 2,097,152

// Scratch (allocation-free rule: __device__ globals)
__device__ float g_qn[ROWS*DDIM];
__device__ float g_q [ROWS*DDIM];
__device__ float g_k [ROWS*DDIM];
__device__ float g_v [ROWS*DDIM];
__device__ float g_ctx[ROWS*DDIM];

// ---------------------------------------------------------------------------
// helpers
// ---------------------------------------------------------------------------
__device__ __forceinline__ unsigned tf32_bits(float x) {
    unsigned u;
    asm("cvt.rna.tf32.f32 %0, %1;" : "=r"(u) : "f"(x));
    return u;
}
__device__ __forceinline__ float tf32f(float x) { return __uint_as_float(tf32_bits(x)); }

__device__ __forceinline__ void mma_tf32(float acc[4], const unsigned a[4], const unsigned b[2]) {
    asm volatile(
        "mma.sync.aligned.m16n8k8.row.col.f32.tf32.tf32.f32 "
        "{%0,%1,%2,%3}, {%4,%5,%6,%7}, {%8,%9}, {%0,%1,%2,%3};"
        : "+f"(acc[0]), "+f"(acc[1]), "+f"(acc[2]), "+f"(acc[3])
        : "r"(a[0]), "r"(a[1]), "r"(a[2]), "r"(a[3]), "r"(b[0]), "r"(b[1]));
}

// FMA-pipe exp(x) via 2^t decomposition, no MUFU. t = x*log2e.
__device__ __forceinline__ float exp_poly_t(float t) {
    t = fmaxf(t, -126.0f);
    const float MAGIC = 12582912.0f;       // 2^23 * 1.5
    float z = t + MAGIC;
    int   i = __float_as_int(z);
    float r = t - (z - MAGIC);             // r in [-0.5, 0.5]
    float p = 0.00133335581f;
    p = fmaf(p, r, 0.00961804886f);
    p = fmaf(p, r, 0.0555041086f);
    p = fmaf(p, r, 0.240226507f);
    p = fmaf(p, r, 0.693147182f);
    p = fmaf(p, r, 1.0f);
    float s = __int_as_float((i - 0x4B400000 + 127) << 23);
    return p * s;
}

// cp.async helpers
__device__ __forceinline__ unsigned smem_u32p(const void* p) {
    return (unsigned)__cvta_generic_to_shared(p);
}
#define CP_ASYNC16(dst, src) asm volatile("cp.async.cg.shared.global [%0], [%1], 16;" :: "r"(dst), "l"(src))
#define CP_COMMIT() asm volatile("cp.async.commit_group;" ::: "memory")
#define CP_WAIT1()  asm volatile("cp.async.wait_group 1;" ::: "memory")
#define CP_WAIT0()  asm volatile("cp.async.wait_group 0;" ::: "memory")

// stage a 64-row x 64-float tile (gmem row stride DDIM) into smem [64][stride]
__device__ __forceinline__ void stage64(const float* __restrict__ g,
                                        float* __restrict__ s, int stride, int tid)
{
    #pragma unroll
    for (int j = 0; j < 4; j++) {
        const int c = tid + j*256;
        const int row = c >> 4;
        const int col = (c & 15) * 4;
        CP_ASYNC16(smem_u32p(&s[row*stride + col]), g + (size_t)row*DDIM + col);
    }
}

// ---------------------------------------------------------------------------
// LayerNorm
// ---------------------------------------------------------------------------
__global__ __launch_bounds__(256)
void ln_kernel(const float* __restrict__ x, const float* __restrict__ gamma,
               const float* __restrict__ beta, float* __restrict__ out)
{
    __shared__ float red[256];
    const int row = blockIdx.x;
    const int tid = threadIdx.x;
    float4 v = ((const float4*)(x + (size_t)row*DDIM))[tid];

    float s = v.x + v.y + v.z + v.w;
    red[tid] = s; __syncthreads();
    #pragma unroll
    for (int o = 128; o > 0; o >>= 1) { if (tid < o) red[tid] += red[tid+o]; __syncthreads(); }
    const float mean = red[0] * (1.0f/DDIM);
    __syncthreads();

    float dx0 = v.x-mean, dx1 = v.y-mean, dx2 = v.z-mean, dx3 = v.w-mean;
    float s2 = dx0*dx0 + dx1*dx1 + dx2*dx2 + dx3*dx3;
    red[tid] = s2; __syncthreads();
    #pragma unroll
    for (int o = 128; o > 0; o >>= 1) { if (tid < o) red[tid] += red[tid+o]; __syncthreads(); }
    const float var = red[0] * (1.0f/DDIM);
    const float rstd = rsqrtf(var + 1e-6f);

    float4 g = ((const float4*)gamma)[tid];
    float4 b = ((const float4*)beta )[tid];
    float4 o4;
    o4.x = dx0*rstd*g.x + b.x;
    o4.y = dx1*rstd*g.y + b.y;
    o4.z = dx2*rstd*g.z + b.z;
    o4.w = dx3*rstd*g.w + b.w;
    ((float4*)(out + (size_t)row*DDIM))[tid] = o4;
}

// ---------------------------------------------------------------------------
// tf32 tensor-core NT GEMM body: 64x128 block tile, k-step 16, double buffer.
// ---------------------------------------------------------------------------
#define SSTR 20

__device__ __forceinline__
void gemm_body(const float* __restrict__ A, const float* __restrict__ W,
               const float* __restrict__ bias, const float* __restrict__ resid,
               float* __restrict__ C, int N, int K, int roundOut,
               float* As0, float* As1, float* Bs0, float* Bs1)
{
    float* AsArr[2] = {As0, As1};
    float* BsArr[2] = {Bs0, Bs1};

    const int tid  = threadIdx.x;
    const int lane = tid & 31;
    const int warp = tid >> 5;
    const int wm   = warp >> 2;
    const int wn   = warp & 3;
    const int gid  = lane >> 2;
    const int tig  = lane & 3;

    const int rowBase = blockIdx.y * 64;
    const int colBase = blockIdx.x * 128;

    const int lr = tid >> 2;
    const int lc = (tid & 3) * 4;
    const float* Ag = A + (size_t)(rowBase + lr) * K + lc;
    const float* Wg = W + (size_t)(colBase + lr) * K + lc;

    float acc[2][4][4];
    #pragma unroll
    for (int mt = 0; mt < 2; mt++)
        #pragma unroll
        for (int nt = 0; nt < 4; nt++)
            #pragma unroll
            for (int c = 0; c < 4; c++) acc[mt][nt][c] = 0.0f;

    float4 pa0, pb0, pb1;
    pa0 = *(const float4*)(Ag);
    pb0 = *(const float4*)(Wg);
    pb1 = *(const float4*)(Wg + (size_t)64*K);
    {
        float4 ca0 = {tf32f(pa0.x), tf32f(pa0.y), tf32f(pa0.z), tf32f(pa0.w)};
        float4 cb0 = {tf32f(pb0.x), tf32f(pb0.y), tf32f(pb0.z), tf32f(pb0.w)};
        float4 cb1 = {tf32f(pb1.x), tf32f(pb1.y), tf32f(pb1.z), tf32f(pb1.w)};
        *(float4*)&AsArr[0][lr*SSTR + lc] = ca0;
        *(float4*)&BsArr[0][lr*SSTR + lc] = cb0;
        *(float4*)&BsArr[0][(lr+64)*SSTR + lc] = cb1;
    }
    __syncthreads();

    int buf = 0;
    for (int k0 = 0; k0 < K; k0 += 16) {
        const bool hasNext = (k0 + 16) < K;
        if (hasNext) {
            pa0 = *(const float4*)(Ag + k0 + 16);
            pb0 = *(const float4*)(Wg + k0 + 16);
            pb1 = *(const float4*)(Wg + (size_t)64*K + k0 + 16);
        }

        const float* Asb = AsArr[buf];
        const float* Bsb = BsArr[buf];
        #pragma unroll
        for (int ks = 0; ks < 16; ks += 8) {
            unsigned afr[2][4];
            #pragma unroll
            for (int mt = 0; mt < 2; mt++) {
                const float* ap = &Asb[(wm*32 + mt*16)*SSTR + ks];
                afr[mt][0] = __float_as_uint(ap[ gid     *SSTR + tig    ]);
                afr[mt][1] = __float_as_uint(ap[(gid + 8)*SSTR + tig    ]);
                afr[mt][2] = __float_as_uint(ap[ gid     *SSTR + tig + 4]);
                afr[mt][3] = __float_as_uint(ap[(gid + 8)*SSTR + tig + 4]);
            }
            unsigned bfr[4][2];
            #pragma unroll
            for (int nt = 0; nt < 4; nt++) {
                const float* bp = &Bsb[(wn*32 + nt*8)*SSTR + ks];
                bfr[nt][0] = __float_as_uint(bp[gid*SSTR + tig    ]);
                bfr[nt][1] = __float_as_uint(bp[gid*SSTR + tig + 4]);
            }
            #pragma unroll
            for (int mt = 0; mt < 2; mt++)
                #pragma unroll
                for (int nt = 0; nt < 4; nt++)
                    mma_tf32(acc[mt][nt], afr[mt], bfr[nt]);
        }

        if (hasNext) {
            const int nb = buf ^ 1;
            float4 ca0 = {tf32f(pa0.x), tf32f(pa0.y), tf32f(pa0.z), tf32f(pa0.w)};
            float4 cb0 = {tf32f(pb0.x), tf32f(pb0.y), tf32f(pb0.z), tf32f(pb0.w)};
            float4 cb1 = {tf32f(pb1.x), tf32f(pb1.y), tf32f(pb1.z), tf32f(pb1.w)};
            *(float4*)&AsArr[nb][lr*SSTR + lc] = ca0;
            *(float4*)&BsArr[nb][lr*SSTR + lc] = cb0;
            *(float4*)&BsArr[nb][(lr+64)*SSTR + lc] = cb1;
            __syncthreads();
            buf = nb;
        }
    }

    #pragma unroll
    for (int nt = 0; nt < 4; nt++) {
        const int col = colBase + wn*32 + nt*8 + tig*2;
        float2 bz = *(const float2*)&bias[col];
        #pragma unroll
        for (int mt = 0; mt < 2; mt++) {
            const int r0 = rowBase + wm*32 + mt*16 + gid;
            const int r1 = r0 + 8;
            float2 v0 = { acc[mt][nt][0] + bz.x, acc[mt][nt][1] + bz.y };
            float2 v1 = { acc[mt][nt][2] + bz.x, acc[mt][nt][3] + bz.y };
            if (resid) {
                float2 q0 = *(const float2*)&resid[(size_t)r0*N + col];
                float2 q1 = *(const float2*)&resid[(size_t)r1*N + col];
                v0.x += q0.x; v0.y += q0.y;
                v1.x += q1.x; v1.y += q1.y;
            }
            if (roundOut) {
                v0.x = tf32f(v0.x); v0.y = tf32f(v0.y);
                v1.x = tf32f(v1.x); v1.y = tf32f(v1.y);
            }
            *(float2*)&C[(size_t)r0*N + col] = v0;
            *(float2*)&C[(size_t)r1*N + col] = v1;
        }
    }
}

__global__ __launch_bounds__(256)
void qkv_gemm(const float* __restrict__ qn, const float* __restrict__ query,
              const float* __restrict__ Wq, const float* __restrict__ Wk, const float* __restrict__ Wv,
              const float* __restrict__ bq, const float* __restrict__ bk, const float* __restrict__ bv,
              float* __restrict__ Qm, float* __restrict__ Km, float* __restrict__ Vm)
{
    __shared__ float As[2][64*SSTR];
    __shared__ float Bs[2][128*SSTR];
    const int z = blockIdx.z;
    const float* A = (z == 0) ? qn : query;
    const float* W = (z == 0) ? Wq : (z == 1) ? Wk : Wv;
    const float* b = (z == 0) ? bq : (z == 1) ? bk : bv;
    float* C       = (z == 0) ? Qm : (z == 1) ? Km : Vm;
    gemm_body(A, W, b, nullptr, C, DDIM, DDIM, 1, As[0], As[1], Bs[0], Bs[1]);
}

__global__ __launch_bounds__(256)
void out_gemm(const float* __restrict__ A, const float* __restrict__ W,
              const float* __restrict__ bias, const float* __restrict__ resid,
              float* __restrict__ C)
{
    __shared__ float As[2][64*SSTR];
    __shared__ float Bs[2][128*SSTR];
    gemm_body(A, W, bias, resid, C, DDIM, DDIM, 0, As[0], As[1], Bs[0], Bs[1]);
}

// ---------------------------------------------------------------------------
// Fused attention with cp.async double-buffered K/V staging.
// q-tile = 16, s-tile = 64, 256 threads, 2 CTAs/SM. Q/K/V pre-rounded tf32.
// ---------------------------------------------------------------------------
#define QT 16
#define ST2 64
#define NTIL (LLE/ST2)               // 16
#define S_STR 1036
#define K_STR 68
#define V_STR 72
#define KVBUF 4608                   // 64*72 floats, fits K (64*68) too
#define SMO_KV (QT*S_STR)            // 16576
#define SMO_Q  (SMO_KV + 2*KVBUF)    // 25792
#define SM_FLOATS (SMO_Q + QT*K_STR) // 26880
#define SM_BYTES (SM_FLOATS*4)       // 107520 B

__global__ void __launch_bounds__(256, 2)
attn_fused(const float* __restrict__ Qg, const float* __restrict__ Kg,
           const float* __restrict__ Vg,
           const float* __restrict__ pos_bias, const float* __restrict__ postag,
           const float* __restrict__ lex, const int* __restrict__ mask,
           float* __restrict__ attn, float* __restrict__ ctx)
{
    extern __shared__ float sm[];
    float* S   = sm;                     // [QT][S_STR]
    float* KV0 = sm + SMO_KV;            // staging buffer 0
    float* KV1 = sm + SMO_KV + KVBUF;    // staging buffer 1
    float* Qs  = sm + SMO_Q;             // [QT][K_STR]

    const int tid  = threadIdx.x;
    const int lane = tid & 31;
    const int w    = tid >> 5;
    const int gid  = lane >> 2;
    const int tig  = lane & 3;
    const int qBase = blockIdx.x * QT;
    const int bh = blockIdx.y;
    const int b = bh >> 4, h = bh & 15;

    const float* Kbase = Kg + (size_t)(b*LLE)*DDIM + h*DK;
    const float* Vbase = Vg + (size_t)(b*LLE)*DDIM + h*DK;

    // group 0: Q tile + K tile 0 ; group 1: K tile 1
    {
        const int row = tid >> 4;
        const int col = (tid & 15) * 4;
        CP_ASYNC16(smem_u32p(&Qs[row*K_STR + col]),
                   Qg + (size_t)(b*LLE + qBase + row)*DDIM + h*DK + col);
    }
    stage64(Kbase, KV0, K_STR, tid);
    CP_COMMIT();
    stage64(Kbase + (size_t)ST2*DDIM, KV1, K_STR, tid);
    CP_COMMIT();

    float qf[8][4];   // Q fragments, loaded once at t==0

    // ---- QK phase ----
    for (int t = 0; t < NTIL; t++) {
        const int s0 = t * ST2;
        // epilogue operand prefetch (independent of smem)
        const int sg = s0 + w*8 + tig*2;
        const float2 lx = *(const float2*)&lex [b*LLE + sg];
        const int2   mk = *(const int2 *)&mask[b*LLE + sg];
        const int r0g = qBase + gid;
        const int r1g = r0g + 8;
        const float2 pb0 = *(const float2*)&pos_bias[((size_t)h*LLE + r0g)*LLE + sg];
        const float2 pb1 = *(const float2*)&pos_bias[((size_t)h*LLE + r1g)*LLE + sg];
        const float2 pt0 = *(const float2*)&postag  [((size_t)bh*LLE + r0g)*LLE + sg];
        const float2 pt1 = *(const float2*)&postag  [((size_t)bh*LLE + r1g)*LLE + sg];

        if (t + 1 < NTIL) CP_WAIT1(); else CP_WAIT0();
        __syncthreads();

        if (t == 0) {
            #pragma unroll
            for (int k8 = 0; k8 < 8; k8++) {
                qf[k8][0] = Qs[ gid     *K_STR + k8*8 + tig    ];
                qf[k8][1] = Qs[(gid + 8)*K_STR + k8*8 + tig    ];
                qf[k8][2] = Qs[ gid     *K_STR + k8*8 + tig + 4];
                qf[k8][3] = Qs[(gid + 8)*K_STR + k8*8 + tig + 4];
            }
        }

        const float* Kb = (t & 1) ? KV1 : KV0;
        float acc[4] = {0.0f, 0.0f, 0.0f, 0.0f};
        #pragma unroll
        for (int k8 = 0; k8 < 8; k8++) {
            const float* bp = &Kb[(w*8 + gid)*K_STR + k8*8];
            unsigned bf[2];
            bf[0] = __float_as_uint(bp[tig    ]);
            bf[1] = __float_as_uint(bp[tig + 4]);
            unsigned af[4];
            af[0] = __float_as_uint(qf[k8][0]);
            af[1] = __float_as_uint(qf[k8][1]);
            af[2] = __float_as_uint(qf[k8][2]);
            af[3] = __float_as_uint(qf[k8][3]);
            mma_tf32(acc, af, bf);
        }

        // epilogue: scale + biases + mask -> S
        {
            float2 v0, v1;
            v0.x = (mk.x == 0) ? -1e30f : (acc[0]*0.125f + pb0.x + pt0.x + lx.x);
            v0.y = (mk.y == 0) ? -1e30f : (acc[1]*0.125f + pb0.y + pt0.y + lx.y);
            v1.x = (mk.x == 0) ? -1e30f : (acc[2]*0.125f + pb1.x + pt1.x + lx.x);
            v1.y = (mk.y == 0) ? -1e30f : (acc[3]*0.125f + pb1.y + pt1.y + lx.y);
            *(float2*)&S[ gid     *S_STR + sg] = v0;
            *(float2*)&S[(gid + 8)*S_STR + sg] = v1;
        }
        __syncthreads();

        if (t + 2 < NTIL) {
            stage64(Kbase + (size_t)(s0 + 2*ST2)*DDIM, (t & 1) ? KV1 : KV0, K_STR, tid);
            CP_COMMIT();
        }
    }

    // prefetch first two V tiles; latency hides under softmax
    stage64(Vbase, KV0, V_STR, tid);
    CP_COMMIT();
    stage64(Vbase + (size_t)ST2*DDIM, KV1, V_STR, tid);
    CP_COMMIT();

    // ---- softmax: warp w handles rows 2w, 2w+1; hybrid MUFU/poly exp ----
    #pragma unroll
    for (int rr = 0; rr < 2; rr++) {
        const int r = w*2 + rr;
        float4 vals[8];
        float m = -3.4e38f;
        #pragma unroll
        for (int i = 0; i < 8; i++) {
            vals[i] = *(const float4*)&S[r*S_STR + (i*32 + lane)*4];
            m = fmaxf(m, fmaxf(fmaxf(vals[i].x, vals[i].y), fmaxf(vals[i].z, vals[i].w)));
        }
        #pragma unroll
        for (int o = 16; o > 0; o >>= 1) m = fmaxf(m, __shfl_xor_sync(0xffffffffu, m, o));

        const float LOG2E = 1.4426950408889634f;
        const float mLog = m * LOG2E;

        float sum = 0.0f;
        #pragma unroll
        for (int i = 0; i < 8; i++) {
            if ((i & 3) == 3) {
                vals[i].x = exp_poly_t(fmaf(vals[i].x, LOG2E, -mLog));
                vals[i].y = exp_poly_t(fmaf(vals[i].y, LOG2E, -mLog));
                vals[i].z = exp_poly_t(fmaf(vals[i].z, LOG2E, -mLog));
                vals[i].w = exp_poly_t(fmaf(vals[i].w, LOG2E, -mLog));
            } else {
                vals[i].x = __expf(vals[i].x - m);
                vals[i].y = __expf(vals[i].y - m);
                vals[i].z = __expf(vals[i].z - m);
                vals[i].w = __expf(vals[i].w - m);
            }
            sum += vals[i].x + vals[i].y + vals[i].z + vals[i].w;
        }
        #pragma unroll
        for (int o = 16; o > 0; o >>= 1) sum += __shfl_xor_sync(0xffffffffu, sum, o);
        const float inv = 1.0f / sum;

        float* arow = &attn[((size_t)bh*LLE + qBase + r)*LLE];
        #pragma unroll
        for (int i = 0; i < 8; i++) {
            float4 p;
            p.x = vals[i].x * inv; p.y = vals[i].y * inv;
            p.z = vals[i].z * inv; p.w = vals[i].w * inv;
            *(float4*)&arow[(i*32 + lane)*4] = p;                // exact fp32 attn
            float4 pt = {tf32f(p.x), tf32f(p.y), tf32f(p.z), tf32f(p.w)};
            *(float4*)&S[r*S_STR + (i*32 + lane)*4] = pt;        // tf32 for AV
        }
    }
    __syncthreads();

    // ---- AV phase: warp w handles out cols [w*8, w*8+8) ----
    float av[4] = {0.0f, 0.0f, 0.0f, 0.0f};
    for (int t = 0; t < NTIL; t++) {
        if (t + 1 < NTIL) CP_WAIT1(); else CP_WAIT0();
        __syncthreads();

        const float* Vb = (t & 1) ? KV1 : KV0;
        #pragma unroll
        for (int k8 = 0; k8 < 8; k8++) {
            const int kk = t*ST2 + k8*8;
            unsigned af[4];
            af[0] = __float_as_uint(S[ gid     *S_STR + kk + tig    ]);
            af[1] = __float_as_uint(S[(gid + 8)*S_STR + kk + tig    ]);
            af[2] = __float_as_uint(S[ gid     *S_STR + kk + tig + 4]);
            af[3] = __float_as_uint(S[(gid + 8)*S_STR + kk + tig + 4]);
            unsigned bf[2];
            bf[0] = __float_as_uint(Vb[(k8*8 + tig    )*V_STR + w*8 + gid]);
            bf[1] = __float_as_uint(Vb[(k8*8 + tig + 4)*V_STR + w*8 + gid]);
            mma_tf32(av, af, bf);
        }
        __syncthreads();

        if (t + 2 < NTIL) {
            stage64(Vbase + (size_t)(t + 2)*ST2*DDIM, (t & 1) ? KV1 : KV0, V_STR, tid);
            CP_COMMIT();
        }
    }

    // write ctx
    {
        const int cc = h*DK + w*8 + tig*2;
        const int r0 = b*LLE + qBase + gid;
        float2 o0 = {av[0], av[1]};
        float2 o1 = {av[2], av[3]};
        *(float2*)&ctx[(size_t)r0*DDIM + cc] = o0;
        *(float2*)&ctx[(size_t)(r0+8)*DDIM + cc] = o1;
    }
}

// ---------------------------------------------------------------------------
extern "C" void kernel_launch(void* const* d_in, const int* in_sizes, int n_in,
                              void* d_out, int out_size)
{
    const float* query  = (const float*)d_in[0];
    const float* pos_b  = (const float*)d_in[1];
    const float* postag = (const float*)d_in[2];
    const float* lex    = (const float*)d_in[3];
    const int*   mask   = (const int*  )d_in[4];
    const float* Wq = (const float*)d_in[5];
    const float* bq = (const float*)d_in[6];
    const float* Wk = (const float*)d_in[7];
    const float* bk = (const float*)d_in[8];
    const float* Wv = (const float*)d_in[9];
    const float* bv = (const float*)d_in[10];
    const float* Wo = (const float*)d_in[11];
    const float* bo = (const float*)d_in[12];
    const float* gamma = (const float*)d_in[13];
    const float* beta  = (const float*)d_in[14];

    float* out  = (float*)d_out;             // (B,L,D)
    float* attn = (float*)d_out + OUT_ELEMS; // (B,H,L,L)

    float* qn  = nullptr; cudaGetSymbolAddress((void**)&qn,  g_qn);
    float* Qm  = nullptr; cudaGetSymbolAddress((void**)&Qm,  g_q);
    float* Km  = nullptr; cudaGetSymbolAddress((void**)&Km,  g_k);
    float* Vm  = nullptr; cudaGetSymbolAddress((void**)&Vm,  g_v);
    float* ctx = nullptr; cudaGetSymbolAddress((void**)&ctx, g_ctx);

    cudaFuncSetAttribute(attn_fused, cudaFuncAttributeMaxDynamicSharedMemorySize, SM_BYTES);

    // 1) pre-LN on query only
    ln_kernel<<<ROWS, 256>>>(query, gamma, beta, qn);

    // 2) Q/K/V projections in one launch (768 CTAs), outputs pre-rounded tf32
    dim3 qkvGrid(DDIM/128, ROWS/64, 3);
    qkv_gemm<<<qkvGrid, 256>>>(qn, query, Wq, Wk, Wv, bq, bk, bv, Qm, Km, Vm);

    // 3) fused logits + softmax + AV
    dim3 aGrid(LLE/QT, BB*HH);
    attn_fused<<<aGrid, 256, SM_BYTES>>>(Qm, Km, Vm, pos_b, postag, lex, mask, attn, ctx);

    // 4) out = ctx @ Wo^T + bo + residual(query)
    dim3 oGrid(DDIM/128, ROWS/64);
    out_gemm<<<oGrid, 256>>>(ctx, Wo, bo, query, out);
}